// round 10
// baseline (speedup 1.0000x reference)
#include <cuda_runtime.h>
#include <cuda_bf16.h>
#include <cuda_fp16.h>
#include <cstdint>

#define NNODE 20000
#define MPAD  20480
#define FEAT  512
#define EMAX  320000
#define FF    (FEAT*FEAT)
#define BN_EPS 1e-5f

#if defined(__CUDA_ARCH_FEAT_SM103_ALL) || defined(__CUDA_ARCH_FEAT_SM100_ALL) || defined(__CUDA_ARCH_FEAT_SM101_ALL)
#define HAS_TCGEN05 1
#else
#define HAS_TCGEN05 0
#endif

// ================= device scratch (static, no allocs) =================
__device__ __half g_Ap[(size_t)MPAD * 2048];   // self slot [0,512) = gather source
__device__ __half g_Ad[(size_t)MPAD * 1024];
__device__ __half g_Bp_hi[2][512 * 2048];
__device__ __half g_Bp_lo[2][512 * 2048];
__device__ __half g_Bd_hi[2][512 * 1024];
__device__ __half g_Bd_lo[2][512 * 1024];
__device__ __half g_Bq_hi[2][512 * 512];
__device__ __half g_Bq_lo[2][512 * 512];
__device__ float g_biasP[2][FEAT];
__device__ float g_biasD[2][FEAT];
__device__ float g_rawd[(size_t)NNODE * FEAT];
__device__ float g_rawp[(size_t)NNODE * FEAT];
__device__ float g_bnstat[4 * FEAT];   // [d_sum, d_sq, p_sum, p_sq]
__device__ int   g_cnt[4 * NNODE];
__device__ int   g_cur[4 * NNODE];
__device__ int   g_off[4 * (NNODE + 1)];
__device__ int   g_adj[4 * EMAX];

// ================= PTX helpers =================
__device__ __forceinline__ uint32_t smem_to_u32(const void* p) {
    uint32_t a;
    asm("{ .reg .u64 t; cvta.to.shared.u64 t, %1; cvt.u32.u64 %0, t; }" : "=r"(a) : "l"(p));
    return a;
}
__device__ __forceinline__ uint32_t elect_one_pred() {
    uint32_t pred;
    asm volatile("{\n\t.reg .pred p;\n\telect.sync _|p, 0xFFFFFFFF;\n\tselp.b32 %0, 1, 0, p;\n\t}" : "=r"(pred));
    return pred;
}
#define SMEM_SWIZZLE_64B(o) ((o) ^ (((o) >> 3) & 0x30))
static constexpr uint64_t SMEM_DESC_BASE_SW64 =
    (uint64_t(4) << 61) | (uint64_t(1) << 46) | (uint64_t(32) << 32) | (uint64_t(1) << 16);
#define MAKE_SMEM_DESC64(base) (SMEM_DESC_BASE_SW64 | ((uint64_t)((base) >> 4) & 0x3FFF))

#define CP_ASYNC16(dst, src) \
    asm volatile("cp.async.cg.shared.global [%0], [%1], 16;" :: "r"(dst), "l"(src) : "memory")
#define CP_COMMIT() asm volatile("cp.async.commit_group;" ::: "memory")
#define CP_WAIT2() asm volatile("cp.async.wait_group 2;" ::: "memory")
#define CP_WAIT1() asm volatile("cp.async.wait_group 1;" ::: "memory")
#define CP_WAIT0() asm volatile("cp.async.wait_group 0;" ::: "memory")

#if HAS_TCGEN05
#define TCGEN05_ALLOC(sm, n) \
    asm volatile("tcgen05.alloc.cta_group::1.sync.aligned.shared::cta.b32 [%0], %1;" \
                 :: "r"((uint32_t)(sm)), "r"((uint32_t)(n)) : "memory")
#define TCGEN05_DEALLOC(t, n) \
    asm volatile("tcgen05.dealloc.cta_group::1.sync.aligned.b32 %0, %1;" :: "r"(t), "r"((uint32_t)(n)))
#define TCGEN05_RELINQ() \
    asm volatile("tcgen05.relinquish_alloc_permit.cta_group::1.sync.aligned;")
#define TCGEN05_COMMIT(mb) \
    asm volatile("tcgen05.commit.cta_group::1.mbarrier::arrive::one.shared::cluster.b64 [%0];" \
                 :: "r"((uint32_t)(mb)) : "memory")
#define TCGEN05_WAIT_LD()  asm volatile("tcgen05.wait::ld.sync.aligned;" ::: "memory")
#define TCGEN05_FENCE_BEFORE() asm volatile("tcgen05.fence::before_thread_sync;" ::: "memory")
#define TCGEN05_FENCE_AFTER()  asm volatile("tcgen05.fence::after_thread_sync;" ::: "memory")
#define FENCE_ASYNC_SHARED() asm volatile("fence.proxy.async.shared::cta;" ::: "memory")
#define MBARRIER_INIT(mb, c) \
    asm volatile("mbarrier.init.shared.b64 [%0], %1;" :: "r"((uint32_t)(mb)), "r"((uint32_t)(c)) : "memory")
#define MBARRIER_INVAL(mb) \
    asm volatile("mbarrier.inval.shared.b64 [%0];" :: "r"((uint32_t)(mb)) : "memory")
#define MBARRIER_WAIT_PARITY(mb, ph) do { \
    uint32_t _mb = (uint32_t)(mb), _ph = (uint32_t)(ph), _done; \
    asm volatile("{\n\t.reg .pred p;\n\tmbarrier.try_wait.parity.acquire.cta.shared::cta.b64 p, [%1], %2;\n\tselp.b32 %0, 1, 0, p;\n\t}" \
        : "=r"(_done) : "r"(_mb), "r"(_ph) : "memory"); \
    if (!_done) { \
        asm volatile("{\n\t.reg .pred P1;\n\tWL_%=: \n\tmbarrier.try_wait.parity.acquire.cta.shared::cta.b64 P1, [%0], %1, 0x989680;\n\t@P1 bra.uni WD_%=;\n\tbra.uni WL_%=;\n\tWD_%=: \n\t}" \
            :: "r"(_mb), "r"(_ph) : "memory"); \
    } \
} while (0)

#define TCGEN05_LD_X32(r, addr) \
    asm volatile("tcgen05.ld.sync.aligned.32x32b.x32.b32 " \
        "{%0, %1, %2, %3, %4, %5, %6, %7, %8, %9, %10, %11, %12, %13, %14, %15, " \
        " %16, %17, %18, %19, %20, %21, %22, %23, %24, %25, %26, %27, %28, %29, %30, %31}, [%32];" \
        : "=r"((r)[0]), "=r"((r)[1]), "=r"((r)[2]), "=r"((r)[3]), "=r"((r)[4]), "=r"((r)[5]), "=r"((r)[6]), "=r"((r)[7]), \
          "=r"((r)[8]), "=r"((r)[9]), "=r"((r)[10]), "=r"((r)[11]), "=r"((r)[12]), "=r"((r)[13]), "=r"((r)[14]), "=r"((r)[15]), \
          "=r"((r)[16]), "=r"((r)[17]), "=r"((r)[18]), "=r"((r)[19]), "=r"((r)[20]), "=r"((r)[21]), "=r"((r)[22]), "=r"((r)[23]), \
          "=r"((r)[24]), "=r"((r)[25]), "=r"((r)[26]), "=r"((r)[27]), "=r"((r)[28]), "=r"((r)[29]), "=r"((r)[30]), "=r"((r)[31]) \
        : "r"(addr))

__device__ __forceinline__ void mma_f16_ss(uint32_t d_tmem, uint64_t a_desc, uint64_t b_desc,
                                           uint32_t idesc, uint32_t enable) {
    asm volatile(
        "{\n\t.reg .pred p;\n\tsetp.ne.u32 p, %5, 0;\n\t"
        "tcgen05.mma.cta_group::1.kind::f16 [%0], %1, %2, %3, {%4, %4, %4, %4}, p;\n\t}"
        :: "r"(d_tmem), "l"(a_desc), "l"(b_desc), "r"(idesc), "r"(0u), "r"(enable)
        : "memory");
}
#endif // HAS_TCGEN05

__device__ __forceinline__ void splith(float v, __half& h, __half& l) {
    h = __float2half_rn(v);
    l = __float2half_rn(v - __half2float(h));
}

// ================= CSR build =================
__global__ void hist_kernel(const int* __restrict__ a_src, const int* __restrict__ a_dst,
                            const int* __restrict__ i_src, const int* __restrict__ i_dst, int E) {
    int i = blockIdx.x * blockDim.x + threadIdx.x;
    if (i >= 4 * E) return;
    int w = i / E, e = i - w * E;
    int k = (w == 0) ? a_dst[e] : (w == 1) ? a_src[e] : (w == 2) ? i_dst[e] : i_src[e];
    atomicAdd(&g_cnt[w * NNODE + k], 1);
}
__global__ void scan_kernel() {
    int c = blockIdx.x;
    __shared__ int sh[1024];
    __shared__ int carry_sh;
    int tid = threadIdx.x;
    if (tid == 0) { carry_sh = 0; g_off[c * (NNODE + 1)] = 0; }
    __syncthreads();
    for (int base = 0; base < NNODE; base += 1024) {
        int i = base + tid;
        int v = (i < NNODE) ? g_cnt[c * NNODE + i] : 0;
        sh[tid] = v;
        __syncthreads();
        #pragma unroll
        for (int d = 1; d < 1024; d <<= 1) {
            int t = (tid >= d) ? sh[tid - d] : 0;
            __syncthreads();
            sh[tid] += t;
            __syncthreads();
        }
        int incl = sh[tid];
        int carry = carry_sh;
        __syncthreads();
        if (i < NNODE) {
            g_off[c * (NNODE + 1) + i + 1] = carry + incl;
            g_cur[c * NNODE + i] = carry + incl - v;
        }
        if (tid == 1023) carry_sh = carry + sh[1023];
        __syncthreads();
    }
}
__global__ void fill_kernel(const int* __restrict__ a_src, const int* __restrict__ a_dst,
                            const int* __restrict__ i_src, const int* __restrict__ i_dst, int E) {
    int i = blockIdx.x * blockDim.x + threadIdx.x;
    if (i >= 4 * E) return;
    int w = i / E, e = i - w * E;
    int k = (w == 0) ? a_dst[e] : (w == 1) ? a_src[e] : (w == 2) ? i_dst[e] : i_src[e];
    int v = (w == 0) ? a_src[e] : (w == 1) ? a_dst[e] : (w == 2) ? i_src[e] : i_dst[e];
    int pos = atomicAdd(&g_cur[w * NNODE + k], 1);
    g_adj[w * E + pos] = v;
}

// ========== fused 4-way segment-mean gather (also zeros BN stats for this layer) ==========
__global__ void gather4_kernel(const __half* __restrict__ Ad, __half* __restrict__ Ap, int E) {
    if (blockIdx.y == 0 && blockIdx.x < 32) {
        int z = blockIdx.x * 64 + threadIdx.x;
        if (z < 4 * FEAT) g_bnstat[z] = 0.f;
    }
    int c = blockIdx.y;
    const __half* src;
    __half* dst;
    int slda, dlda, coff;
    if (c == 0) { src = Ad; slda = 1024; dst = Ap; dlda = 2048; coff = 512; }
    else if (c == 1) { src = Ap; slda = 2048; dst = (__half*)Ad; dlda = 1024; coff = 512; }
    else { src = Ap; slda = 2048; dst = Ap; dlda = 2048; coff = (c == 2) ? 1024 : 1536; }
    int n = blockIdx.x;
    int t = threadIdx.x;            // 0..63, 8 halves each (16B)
    int s = g_off[c * (NNODE + 1) + n];
    int e = g_off[c * (NNODE + 1) + n + 1];
    const int* adj = g_adj + (size_t)c * E;
    float acc[8] = {0.f, 0.f, 0.f, 0.f, 0.f, 0.f, 0.f, 0.f};
    int j = s;
    for (; j + 3 < e; j += 4) {
        int r0 = adj[j], r1 = adj[j + 1], r2 = adj[j + 2], r3 = adj[j + 3];
        uint4 v0 = *(const uint4*)(src + (size_t)r0 * slda + t * 8);
        uint4 v1 = *(const uint4*)(src + (size_t)r1 * slda + t * 8);
        uint4 v2 = *(const uint4*)(src + (size_t)r2 * slda + t * 8);
        uint4 v3 = *(const uint4*)(src + (size_t)r3 * slda + t * 8);
        const uint4* vs[4] = {&v0, &v1, &v2, &v3};
        #pragma unroll
        for (int q = 0; q < 4; q++) {
            const __half2* h2 = (const __half2*)vs[q];
            #pragma unroll
            for (int p = 0; p < 4; p++) {
                float2 f = __half22float2(h2[p]);
                acc[2 * p] += f.x; acc[2 * p + 1] += f.y;
            }
        }
    }
    for (; j < e; j++) {
        int r0 = adj[j];
        uint4 v0 = *(const uint4*)(src + (size_t)r0 * slda + t * 8);
        const __half2* h2 = (const __half2*)&v0;
        #pragma unroll
        for (int p = 0; p < 4; p++) {
            float2 f = __half22float2(h2[p]);
            acc[2 * p] += f.x; acc[2 * p + 1] += f.y;
        }
    }
    float inv = (e > s) ? 1.0f / (float)(e - s) : 0.0f;
    __half o8[8];
    #pragma unroll
    for (int q = 0; q < 8; q++) o8[q] = __float2half_rn(acc[q] * inv);
    *(uint4*)(dst + (size_t)n * dlda + coff + t * 8) = *(uint4*)&o8[0];
}

// ========== merged fp32->fp16 input conversion into A self slots ==========
__global__ void split2_kernel(const float* __restrict__ h_p, const float* __restrict__ h_d,
                              __half* __restrict__ Ap, __half* __restrict__ Ad) {
    size_t idx = (size_t)blockIdx.x * blockDim.x + threadIdx.x;
    if (idx >= (size_t)NNODE * FEAT) return;
    int row = (int)(idx >> 9), col = (int)(idx & 511);
    const float* src = blockIdx.y ? h_d : h_p;
    __half* A = blockIdx.y ? Ad : Ap;
    int lda = blockIdx.y ? 1024 : 2048;
    A[(size_t)row * lda + col] = __float2half_rn(src[idx]);
}

// ========== weight prep: tiled transpose + fuse + fp16 split (also zeros g_cnt) ==========
__global__ void wprep_kernel(const float* __restrict__ Ws1, const float* __restrict__ Wn1,
                             const float* __restrict__ Ws2, const float* __restrict__ Wn2,
                             const float* __restrict__ pWd, const float* __restrict__ pWp) {
    // fold CSR count zeroing into this first kernel
    {
        int bid = (blockIdx.z * 16 + blockIdx.y) * 16 + blockIdx.x;
        int id = bid * 1024 + threadIdx.y * 32 + threadIdx.x;
        if (id < 4 * NNODE) g_cnt[id] = 0;
    }
    __shared__ float tile[4][32][33];
    int which = blockIdx.z;
    int n0 = blockIdx.x * 32, k0 = blockIdx.y * 32;
    int tx = threadIdx.x, ty = threadIdx.y;
    int srcIdx = (k0 + ty) * 512 + (n0 + tx);
    int nslots;
    __half *Bh, *Bl;
    int ldb;
    if (which == 0 || which == 2) {
        int li = which >> 1;
        const float* Ws = li ? Ws2 : Ws1;
        const float* Wn = li ? Wn2 : Wn1;
        tile[0][ty][tx] = Ws[srcIdx] + Ws[2 * FF + srcIdx] + Ws[3 * FF + srcIdx];
        tile[1][ty][tx] = Wn[srcIdx];
        tile[2][ty][tx] = Wn[2 * FF + srcIdx];
        tile[3][ty][tx] = Wn[3 * FF + srcIdx];
        nslots = 4; Bh = g_Bp_hi[li]; Bl = g_Bp_lo[li]; ldb = 2048;
    } else if (which == 1 || which == 3) {
        int li = which >> 1;
        const float* Ws = li ? Ws2 : Ws1;
        const float* Wn = li ? Wn2 : Wn1;
        tile[0][ty][tx] = Ws[FF + srcIdx];
        tile[1][ty][tx] = Wn[FF + srcIdx];
        nslots = 2; Bh = g_Bd_hi[li]; Bl = g_Bd_lo[li]; ldb = 1024;
    } else {
        int q = which - 4;
        const float* W = q ? pWp : pWd;
        tile[0][ty][tx] = W[srcIdx];
        nslots = 1; Bh = g_Bq_hi[q]; Bl = g_Bq_lo[q]; ldb = 512;
    }
    __syncthreads();
    for (int sl = 0; sl < nslots; sl++) {
        float v = tile[sl][tx][ty];
        __half h, l;
        splith(v, h, l);
        size_t o = (size_t)(n0 + ty) * ldb + sl * 512 + k0 + tx;
        Bh[o] = h; Bl[o] = l;
    }
}
__global__ void bias_kernel(const float* __restrict__ b1, const float* __restrict__ b2) {
    int i = threadIdx.x;
    g_biasP[0][i] = b1[i] + b1[1024 + i] + b1[1536 + i];
    g_biasD[0][i] = b1[512 + i];
    g_biasP[1][i] = b2[i] + b2[1024 + i] + b2[1536 + i];
    g_biasD[1][i] = b2[512 + i];
}

// ================= paired tcgen05 fp16 GEMM, M=512 x N=128, KC=32, 3-stage pipeline =====
// C = A16 * (Bh + Bl) + bias; optional fused BN column stats (sum/sumsq) into `stat`.
struct GPair {
    const __half *A0, *Bh0, *Bl0; const float* bias0; float* C0; float* stat0; int lda0, ldb0, K0;
    const __half *A1, *Bh1, *Bl1; const float* bias1; float* C1; float* stat1; int lda1, ldb1, K1;
};
#define STAGE_BYTES 49152   // A 32K | Bh 8K | Bl 8K
#define GEMM_SMEM (2048 + 3 * STAGE_BYTES)
__global__ __launch_bounds__(128)
void mma_gemm_pair(const GPair gp, int M) {
    const __half* A   = blockIdx.z ? gp.A1 : gp.A0;
    const __half* Bhi = blockIdx.z ? gp.Bh1 : gp.Bh0;
    const __half* Blo = blockIdx.z ? gp.Bl1 : gp.Bl0;
    const float* bias = blockIdx.z ? gp.bias1 : gp.bias0;
    float* C = blockIdx.z ? gp.C1 : gp.C0;
    float* stat = blockIdx.z ? gp.stat1 : gp.stat0;
    const int lda = blockIdx.z ? gp.lda1 : gp.lda0;
    const int ldb = blockIdx.z ? gp.ldb1 : gp.ldb0;
    const int Ktot = blockIdx.z ? gp.K1 : gp.K0;
#if HAS_TCGEN05
    extern __shared__ char smem[];
    uint32_t sb = smem_to_u32(smem);
    float* s_stat = (float*)(smem + 1024);    // 128 sums + 128 sumsqs
    const int tid = threadIdx.x;
    const int wid = tid >> 5, lid = tid & 31;
    const int m0 = blockIdx.y * 512, n0 = blockIdx.x * 128;

    if (wid == 0) { TCGEN05_ALLOC(sb, 512); TCGEN05_RELINQ(); }
    if (tid == 0) MBARRIER_INIT(sb + 8, 1);
    __syncthreads();
    uint32_t tbase;
    asm volatile("ld.shared.b32 %0, [%1];" : "=r"(tbase) : "r"(sb));

    const uint32_t idesc = 0x8200010u;   // F32 acc, F16 A/B, M=128, N=128
    const int nst = Ktot >> 5;           // KC = 32

    auto issue_loads = [&](int s) {
        int k0 = s << 5;
        uint32_t base = sb + 2048 + (uint32_t)(s % 3) * STAGE_BYTES;
        // A: 512 rows x 64B = 2048 chunks; 16 per thread
        #pragma unroll
        for (int c = 0; c < 16; c++) {
            int chunk = c * 128 + tid;
            int row = chunk >> 2, ch = chunk & 3;
            uint32_t sw = SMEM_SWIZZLE_64B((uint32_t)(row * 64 + ch * 16));
            size_t ga = (size_t)(m0 + row) * lda + k0 + ch * 8;
            CP_ASYNC16(base + sw, A + ga);
        }
        // B hi/lo: 128 rows x 64B = 512 chunks each; 4 per thread each
        #pragma unroll
        for (int c = 0; c < 4; c++) {
            int chunk = c * 128 + tid;
            int row = chunk >> 2, ch = chunk & 3;
            uint32_t sw = SMEM_SWIZZLE_64B((uint32_t)(row * 64 + ch * 16));
            size_t gb = (size_t)(n0 + row) * ldb + k0 + ch * 8;
            CP_ASYNC16(base + 32768 + sw, Bhi + gb);
            CP_ASYNC16(base + 40960 + sw, Blo + gb);
        }
        CP_COMMIT();
    };

    issue_loads(0);
    issue_loads(1);
    for (int s = 0; s < nst; s++) {
        if (s >= 1) MBARRIER_WAIT_PARITY(sb + 8, (s - 1) & 1);
        if (s + 2 < nst)      { issue_loads(s + 2); CP_WAIT2(); }
        else if (s + 1 < nst) { CP_WAIT1(); }
        else                  { CP_WAIT0(); }
        __syncthreads();
        FENCE_ASYNC_SHARED();
        if (wid == 0 && elect_one_pred()) {
            uint32_t bufb = sb + 2048 + (uint32_t)(s % 3) * STAGE_BYTES;
            uint64_t dBh = MAKE_SMEM_DESC64(bufb + 32768);
            uint64_t dBl = MAKE_SMEM_DESC64(bufb + 40960);
            #pragma unroll
            for (int kk = 0; kk < 2; kk++) {
                uint64_t o = (uint64_t)(kk * 2);
                uint32_t en0 = !(s == 0 && kk == 0);
                #pragma unroll
                for (int sub = 0; sub < 4; sub++) {
                    uint64_t dA = MAKE_SMEM_DESC64(bufb + sub * 8192) + o;
                    mma_f16_ss(tbase + sub * 128, dA, dBh + o, idesc, en0);
                }
                #pragma unroll
                for (int sub = 0; sub < 4; sub++) {
                    uint64_t dA = MAKE_SMEM_DESC64(bufb + sub * 8192) + o;
                    mma_f16_ss(tbase + sub * 128, dA, dBl + o, idesc, 1u);
                }
            }
            TCGEN05_COMMIT(sb + 8);
        }
    }
    MBARRIER_WAIT_PARITY(sb + 8, (nst - 1) & 1);
    TCGEN05_FENCE_AFTER();

    // zero per-CTA stat smem
    if (stat) {
        s_stat[tid] = 0.f;
        s_stat[tid + 128] = 0.f;
    }
    __syncthreads();

    #pragma unroll
    for (int sub = 0; sub < 4; sub++) {
        int gr = m0 + sub * 128 + wid * 32 + lid;
        uint32_t dt = tbase + sub * 128;
        #pragma unroll
        for (int base = 0; base < 128; base += 32) {
            uint32_t r[32];
            TCGEN05_LD_X32(r, dt + base);
            TCGEN05_WAIT_LD();
            float v32[32];
            #pragma unroll
            for (int j = 0; j < 32; j++)
                v32[j] = __uint_as_float(r[j]) + bias[n0 + base + j];
            if (gr < M) {
                float* cp = C + (size_t)gr * 512 + n0 + base;
                #pragma unroll
                for (int j = 0; j < 32; j += 4)
                    *(float4*)(cp + j) = make_float4(v32[j], v32[j + 1], v32[j + 2], v32[j + 3]);
            }
            if (stat) {
                #pragma unroll
                for (int j = 0; j < 32; j++) {
                    float sv = (gr < M) ? v32[j] : 0.f;
                    float sq = sv * sv;
                    #pragma unroll
                    for (int o = 16; o > 0; o >>= 1) {
                        sv += __shfl_xor_sync(0xFFFFFFFF, sv, o);
                        sq += __shfl_xor_sync(0xFFFFFFFF, sq, o);
                    }
                    if (lid == 0) {
                        atomicAdd(&s_stat[base + j], sv);
                        atomicAdd(&s_stat[128 + base + j], sq);
                    }
                }
            }
        }
    }
    TCGEN05_FENCE_BEFORE();
    __syncthreads();
    if (stat) {
        atomicAdd(&stat[n0 + tid], s_stat[tid]);
        atomicAdd(&stat[512 + n0 + tid], s_stat[128 + tid]);
    }
    if (tid == 0) MBARRIER_INVAL(sb + 8);
    __syncthreads();
    if (wid == 0) TCGEN05_DEALLOC(tbase, 512);
#else
    const int tid = threadIdx.x;
    const int m0 = blockIdx.y * 512, n0 = blockIdx.x * 128;
    for (int rc = tid; rc < 512 * 128; rc += blockDim.x) {
        int r = rc >> 7, c = rc & 127;
        int gr = m0 + r, gc = n0 + c;
        if (gr >= M) continue;
        const __half* a  = A + (size_t)gr * lda;
        const __half* bh = Bhi + (size_t)gc * ldb;
        const __half* bl = Blo + (size_t)gc * ldb;
        float acc = 0.f;
        for (int k = 0; k < Ktot; k++) {
            float av = __half2float(a[k]);
            acc += av * __half2float(bh[k]) + av * __half2float(bl[k]);
        }
        float v = acc + bias[gc];
        C[(size_t)gr * 512 + gc] = v;
        if (stat) {
            atomicAdd(&stat[gc], v);
            atomicAdd(&stat[512 + gc], v * v);
        }
    }
#endif
}

// ================= BatchNorm + ReLU normalize (stats already in g_bnstat) =================
__global__ void bn_norm2_kernel(const float* __restrict__ rawd, const float* __restrict__ rawp,
                                __half* __restrict__ Ad, __half* __restrict__ Ap,
                                const float* __restrict__ gamma_l, const float* __restrict__ beta_l) {
    size_t idx = (size_t)blockIdx.x * blockDim.x + threadIdx.x;
    if (idx >= (size_t)NNODE * FEAT) return;
    int isP = blockIdx.y;
    int col = (int)(idx & (FEAT - 1));
    int row = (int)(idx >> 9);
    const float* raw = isP ? rawp : rawd;
    __half* Ax = isP ? Ap : Ad;
    int lda = isP ? 2048 : 1024;
    int sbase = isP ? 1024 : 0;
    const float* gamma = gamma_l + isP * FEAT;
    const float* beta  = beta_l + isP * FEAT;
    float mean = g_bnstat[sbase + col] * (1.0f / NNODE);
    float var  = g_bnstat[sbase + 512 + col] * (1.0f / NNODE) - mean * mean;
    float sc = gamma[col] * rsqrtf(var + BN_EPS);
    float v = (raw[idx] - mean) * sc + beta[col];
    v = v > 0.f ? v : 0.f;
    Ax[(size_t)row * lda + col] = __float2half_rn(v);
}

// ================= host orchestration =================
extern "C" void kernel_launch(void* const* d_in, const int* in_sizes, int n_in,
                              void* d_out, int out_size) {
    const float* h_d  = (const float*)d_in[0];
    const float* h_p  = (const float*)d_in[1];
    const float* Ws1  = (const float*)d_in[2];
    const float* Wn1  = (const float*)d_in[3];
    const float* b1   = (const float*)d_in[4];
    const float* Ws2  = (const float*)d_in[5];
    const float* Wn2  = (const float*)d_in[6];
    const float* b2   = (const float*)d_in[7];
    const float* gam  = (const float*)d_in[8];
    const float* bet  = (const float*)d_in[9];
    const float* pWd  = (const float*)d_in[10];
    const float* pbd  = (const float*)d_in[11];
    const float* pWp  = (const float*)d_in[12];
    const float* pbp  = (const float*)d_in[13];
    const int* a_src = (const int*)d_in[14];
    const int* a_dst = (const int*)d_in[15];
    const int* i_src = (const int*)d_in[16];
    const int* i_dst = (const int*)d_in[17];
    int E = in_sizes[14];

    float* out_d = (float*)d_out;
    float* out_p = out_d + (size_t)NNODE * FEAT;

    __half *Ap, *Ad, *BpH, *BpL, *BdH, *BdL, *BqH, *BqL;
    float *rawd, *rawp, *biasP, *biasD, *bnstat;
    cudaGetSymbolAddress((void**)&Ap, g_Ap);
    cudaGetSymbolAddress((void**)&Ad, g_Ad);
    cudaGetSymbolAddress((void**)&BpH, g_Bp_hi);
    cudaGetSymbolAddress((void**)&BpL, g_Bp_lo);
    cudaGetSymbolAddress((void**)&BdH, g_Bd_hi);
    cudaGetSymbolAddress((void**)&BdL, g_Bd_lo);
    cudaGetSymbolAddress((void**)&BqH, g_Bq_hi);
    cudaGetSymbolAddress((void**)&BqL, g_Bq_lo);
    cudaGetSymbolAddress((void**)&rawd, g_rawd);
    cudaGetSymbolAddress((void**)&rawp, g_rawp);
    cudaGetSymbolAddress((void**)&biasP, g_biasP);
    cudaGetSymbolAddress((void**)&biasD, g_biasD);
    cudaGetSymbolAddress((void**)&bnstat, g_bnstat);

    cudaFuncSetAttribute(mma_gemm_pair, cudaFuncAttributeMaxDynamicSharedMemorySize, GEMM_SMEM);

    const int NW = (NNODE * FEAT + 255) / 256;
    const int MT = (NNODE + 511) / 512;               // 40
    const dim3 gpair(4, MT, 2);
    const dim3 g4(NNODE, 4);

    GPair lay[2];
    for (int li = 0; li < 2; li++) {
        lay[li].A0 = Ap;
        lay[li].Bh0 = BpH + (size_t)li * 512 * 2048; lay[li].Bl0 = BpL + (size_t)li * 512 * 2048;
        lay[li].bias0 = biasP + li * FEAT; lay[li].C0 = rawp; lay[li].stat0 = bnstat + 1024;
        lay[li].lda0 = 2048; lay[li].ldb0 = 2048; lay[li].K0 = 2048;
        lay[li].A1 = Ad;
        lay[li].Bh1 = BdH + (size_t)li * 512 * 1024; lay[li].Bl1 = BdL + (size_t)li * 512 * 1024;
        lay[li].bias1 = biasD + li * FEAT; lay[li].C1 = rawd; lay[li].stat1 = bnstat;
        lay[li].lda1 = 1024; lay[li].ldb1 = 1024; lay[li].K1 = 1024;
    }
    GPair proj;
    proj.A0 = Ad; proj.Bh0 = BqH; proj.Bl0 = BqL;
    proj.bias0 = pbd; proj.C0 = out_d; proj.stat0 = nullptr;
    proj.lda0 = 1024; proj.ldb0 = 512; proj.K0 = 512;
    proj.A1 = Ap; proj.Bh1 = BqH + FF; proj.Bl1 = BqL + FF;
    proj.bias1 = pbp; proj.C1 = out_p; proj.stat1 = nullptr;
    proj.lda1 = 2048; proj.ldb1 = 512; proj.K1 = 512;

    // ---- prep (wprep also zeros g_cnt) ----
    wprep_kernel<<<dim3(16, 16, 6), dim3(32, 32)>>>(Ws1, Wn1, Ws2, Wn2, pWd, pWp);
    bias_kernel<<<1, 512>>>(b1, b2);
    split2_kernel<<<dim3(NW, 2), 256>>>(h_p, h_d, Ap, Ad);

    // ---- CSR build ----
    hist_kernel<<<(4 * E + 255) / 256, 256>>>(a_src, a_dst, i_src, i_dst, E);
    scan_kernel<<<4, 1024>>>();
    fill_kernel<<<(4 * E + 255) / 256, 256>>>(a_src, a_dst, i_src, i_dst, E);

    // ---- layers ----
    for (int li = 0; li < 2; li++) {
        gather4_kernel<<<g4, 64>>>(Ad, Ap, E);   // also zeros g_bnstat
        mma_gemm_pair<<<gpair, 128, GEMM_SMEM>>>(lay[li], NNODE);   // fused BN stats
        bn_norm2_kernel<<<dim3(NW, 2), 256>>>(rawd, rawp, Ad, Ap,
                                              gam + li * 2 * FEAT, bet + li * 2 * FEAT);
    }

    // ---- projections ----
    mma_gemm_pair<<<gpair, 128, GEMM_SMEM>>>(proj, NNODE);
}

// round 13
// speedup vs baseline: 1.6228x; 1.6228x over previous
#include <cuda_runtime.h>
#include <cuda_bf16.h>
#include <cuda_fp16.h>
#include <cstdint>

#define NNODE 20000
#define MPAD  20480
#define FEAT  512
#define EMAX  320000
#define FF    (FEAT*FEAT)
#define BN_EPS 1e-5f

#if defined(__CUDA_ARCH_FEAT_SM103_ALL) || defined(__CUDA_ARCH_FEAT_SM100_ALL) || defined(__CUDA_ARCH_FEAT_SM101_ALL)
#define HAS_TCGEN05 1
#else
#define HAS_TCGEN05 0
#endif

// ================= device scratch (static, no allocs) =================
__device__ __half g_Ap[(size_t)MPAD * 2048];   // self slot [0,512) = gather source
__device__ __half g_Ad[(size_t)MPAD * 1024];
__device__ __half g_Bp[2][512 * 2048];         // single fp16 weights (transposed, fused)
__device__ __half g_Bd[2][512 * 1024];
__device__ __half g_Bq[2][512 * 512];
__device__ float g_biasP[2][FEAT];
__device__ float g_biasD[2][FEAT];
__device__ float g_rawd[(size_t)NNODE * FEAT];
__device__ float g_rawp[(size_t)NNODE * FEAT];
__device__ float g_bnstat[4 * FEAT];   // [d_sum, d_sq, p_sum, p_sq]
__device__ int   g_cnt[4 * NNODE];
__device__ int   g_cur[4 * NNODE];
__device__ int   g_off[4 * (NNODE + 1)];
__device__ int   g_adj[4 * EMAX];

// ================= PTX helpers =================
__device__ __forceinline__ uint32_t smem_to_u32(const void* p) {
    uint32_t a;
    asm("{ .reg .u64 t; cvta.to.shared.u64 t, %1; cvt.u32.u64 %0, t; }" : "=r"(a) : "l"(p));
    return a;
}
__device__ __forceinline__ uint32_t elect_one_pred() {
    uint32_t pred;
    asm volatile("{\n\t.reg .pred p;\n\telect.sync _|p, 0xFFFFFFFF;\n\tselp.b32 %0, 1, 0, p;\n\t}" : "=r"(pred));
    return pred;
}
#define SMEM_SWIZZLE_64B(o) ((o) ^ (((o) >> 3) & 0x30))
static constexpr uint64_t SMEM_DESC_BASE_SW64 =
    (uint64_t(4) << 61) | (uint64_t(1) << 46) | (uint64_t(32) << 32) | (uint64_t(1) << 16);
#define MAKE_SMEM_DESC64(base) (SMEM_DESC_BASE_SW64 | ((uint64_t)((base) >> 4) & 0x3FFF))

#define CP_ASYNC16(dst, src) \
    asm volatile("cp.async.cg.shared.global [%0], [%1], 16;" :: "r"(dst), "l"(src) : "memory")
#define CP_COMMIT() asm volatile("cp.async.commit_group;" ::: "memory")
#define CP_WAIT3() asm volatile("cp.async.wait_group 3;" ::: "memory")
#define CP_WAIT2() asm volatile("cp.async.wait_group 2;" ::: "memory")
#define CP_WAIT1() asm volatile("cp.async.wait_group 1;" ::: "memory")
#define CP_WAIT0() asm volatile("cp.async.wait_group 0;" ::: "memory")

#if HAS_TCGEN05
#define TCGEN05_ALLOC(sm, n) \
    asm volatile("tcgen05.alloc.cta_group::1.sync.aligned.shared::cta.b32 [%0], %1;" \
                 :: "r"((uint32_t)(sm)), "r"((uint32_t)(n)) : "memory")
#define TCGEN05_DEALLOC(t, n) \
    asm volatile("tcgen05.dealloc.cta_group::1.sync.aligned.b32 %0, %1;" :: "r"(t), "r"((uint32_t)(n)))
#define TCGEN05_RELINQ() \
    asm volatile("tcgen05.relinquish_alloc_permit.cta_group::1.sync.aligned;")
#define TCGEN05_COMMIT(mb) \
    asm volatile("tcgen05.commit.cta_group::1.mbarrier::arrive::one.shared::cluster.b64 [%0];" \
                 :: "r"((uint32_t)(mb)) : "memory")
#define TCGEN05_WAIT_LD()  asm volatile("tcgen05.wait::ld.sync.aligned;" ::: "memory")
#define TCGEN05_FENCE_BEFORE() asm volatile("tcgen05.fence::before_thread_sync;" ::: "memory")
#define TCGEN05_FENCE_AFTER()  asm volatile("tcgen05.fence::after_thread_sync;" ::: "memory")
#define FENCE_ASYNC_SHARED() asm volatile("fence.proxy.async.shared::cta;" ::: "memory")
#define MBARRIER_INIT(mb, c) \
    asm volatile("mbarrier.init.shared.b64 [%0], %1;" :: "r"((uint32_t)(mb)), "r"((uint32_t)(c)) : "memory")
#define MBARRIER_INVAL(mb) \
    asm volatile("mbarrier.inval.shared.b64 [%0];" :: "r"((uint32_t)(mb)) : "memory")
#define MBARRIER_WAIT_PARITY(mb, ph) do { \
    uint32_t _mb = (uint32_t)(mb), _ph = (uint32_t)(ph), _done; \
    asm volatile("{\n\t.reg .pred p;\n\tmbarrier.try_wait.parity.acquire.cta.shared::cta.b64 p, [%1], %2;\n\tselp.b32 %0, 1, 0, p;\n\t}" \
        : "=r"(_done) : "r"(_mb), "r"(_ph) : "memory"); \
    if (!_done) { \
        asm volatile("{\n\t.reg .pred P1;\n\tWL_%=: \n\tmbarrier.try_wait.parity.acquire.cta.shared::cta.b64 P1, [%0], %1, 0x989680;\n\t@P1 bra.uni WD_%=;\n\tbra.uni WL_%=;\n\tWD_%=: \n\t}" \
            :: "r"(_mb), "r"(_ph) : "memory"); \
    } \
} while (0)

#define TCGEN05_LD_X32(r, addr) \
    asm volatile("tcgen05.ld.sync.aligned.32x32b.x32.b32 " \
        "{%0, %1, %2, %3, %4, %5, %6, %7, %8, %9, %10, %11, %12, %13, %14, %15, " \
        " %16, %17, %18, %19, %20, %21, %22, %23, %24, %25, %26, %27, %28, %29, %30, %31}, [%32];" \
        : "=r"((r)[0]), "=r"((r)[1]), "=r"((r)[2]), "=r"((r)[3]), "=r"((r)[4]), "=r"((r)[5]), "=r"((r)[6]), "=r"((r)[7]), \
          "=r"((r)[8]), "=r"((r)[9]), "=r"((r)[10]), "=r"((r)[11]), "=r"((r)[12]), "=r"((r)[13]), "=r"((r)[14]), "=r"((r)[15]), \
          "=r"((r)[16]), "=r"((r)[17]), "=r"((r)[18]), "=r"((r)[19]), "=r"((r)[20]), "=r"((r)[21]), "=r"((r)[22]), "=r"((r)[23]), \
          "=r"((r)[24]), "=r"((r)[25]), "=r"((r)[26]), "=r"((r)[27]), "=r"((r)[28]), "=r"((r)[29]), "=r"((r)[30]), "=r"((r)[31]) \
        : "r"(addr))

__device__ __forceinline__ void mma_f16_ss(uint32_t d_tmem, uint64_t a_desc, uint64_t b_desc,
                                           uint32_t idesc, uint32_t enable) {
    asm volatile(
        "{\n\t.reg .pred p;\n\tsetp.ne.u32 p, %5, 0;\n\t"
        "tcgen05.mma.cta_group::1.kind::f16 [%0], %1, %2, %3, {%4, %4, %4, %4}, p;\n\t}"
        :: "r"(d_tmem), "l"(a_desc), "l"(b_desc), "r"(idesc), "r"(0u), "r"(enable)
        : "memory");
}
#endif // HAS_TCGEN05

// ================= CSR build =================
__global__ void hist_kernel(const int* __restrict__ a_src, const int* __restrict__ a_dst,
                            const int* __restrict__ i_src, const int* __restrict__ i_dst, int E) {
    int i = blockIdx.x * blockDim.x + threadIdx.x;
    if (i >= 4 * E) return;
    int w = i / E, e = i - w * E;
    int k = (w == 0) ? a_dst[e] : (w == 1) ? a_src[e] : (w == 2) ? i_dst[e] : i_src[e];
    atomicAdd(&g_cnt[w * NNODE + k], 1);
}
__global__ void scan_kernel() {
    int c = blockIdx.x;
    __shared__ int sh[1024];
    __shared__ int carry_sh;
    int tid = threadIdx.x;
    if (tid == 0) { carry_sh = 0; g_off[c * (NNODE + 1)] = 0; }
    __syncthreads();
    for (int base = 0; base < NNODE; base += 1024) {
        int i = base + tid;
        int v = (i < NNODE) ? g_cnt[c * NNODE + i] : 0;
        sh[tid] = v;
        __syncthreads();
        #pragma unroll
        for (int d = 1; d < 1024; d <<= 1) {
            int t = (tid >= d) ? sh[tid - d] : 0;
            __syncthreads();
            sh[tid] += t;
            __syncthreads();
        }
        int incl = sh[tid];
        int carry = carry_sh;
        __syncthreads();
        if (i < NNODE) {
            g_off[c * (NNODE + 1) + i + 1] = carry + incl;
            g_cur[c * NNODE + i] = carry + incl - v;
        }
        if (tid == 1023) carry_sh = carry + sh[1023];
        __syncthreads();
    }
}
__global__ void fill_kernel(const int* __restrict__ a_src, const int* __restrict__ a_dst,
                            const int* __restrict__ i_src, const int* __restrict__ i_dst, int E) {
    int i = blockIdx.x * blockDim.x + threadIdx.x;
    if (i >= 4 * E) return;
    int w = i / E, e = i - w * E;
    int k = (w == 0) ? a_dst[e] : (w == 1) ? a_src[e] : (w == 2) ? i_dst[e] : i_src[e];
    int v = (w == 0) ? a_src[e] : (w == 1) ? a_dst[e] : (w == 2) ? i_src[e] : i_dst[e];
    int pos = atomicAdd(&g_cur[w * NNODE + k], 1);
    g_adj[w * E + pos] = v;
}

// ========== fused 4-way segment-mean gather (also zeros BN stats for this layer) ==========
__global__ void gather4_kernel(const __half* __restrict__ Ad, __half* __restrict__ Ap, int E) {
    if (blockIdx.y == 0 && blockIdx.x < 32) {
        int z = blockIdx.x * 64 + threadIdx.x;
        if (z < 4 * FEAT) g_bnstat[z] = 0.f;
    }
    int c = blockIdx.y;
    const __half* src;
    __half* dst;
    int slda, dlda, coff;
    if (c == 0) { src = Ad; slda = 1024; dst = Ap; dlda = 2048; coff = 512; }
    else if (c == 1) { src = Ap; slda = 2048; dst = (__half*)Ad; dlda = 1024; coff = 512; }
    else { src = Ap; slda = 2048; dst = Ap; dlda = 2048; coff = (c == 2) ? 1024 : 1536; }
    int n = blockIdx.x;
    int t = threadIdx.x;            // 0..63, 8 halves each (16B)
    int s = g_off[c * (NNODE + 1) + n];
    int e = g_off[c * (NNODE + 1) + n + 1];
    const int* adj = g_adj + (size_t)c * E;
    float acc[8] = {0.f, 0.f, 0.f, 0.f, 0.f, 0.f, 0.f, 0.f};
    int j = s;
    for (; j + 3 < e; j += 4) {
        int r0 = adj[j], r1 = adj[j + 1], r2 = adj[j + 2], r3 = adj[j + 3];
        uint4 v0 = *(const uint4*)(src + (size_t)r0 * slda + t * 8);
        uint4 v1 = *(const uint4*)(src + (size_t)r1 * slda + t * 8);
        uint4 v2 = *(const uint4*)(src + (size_t)r2 * slda + t * 8);
        uint4 v3 = *(const uint4*)(src + (size_t)r3 * slda + t * 8);
        const uint4* vs[4] = {&v0, &v1, &v2, &v3};
        #pragma unroll
        for (int q = 0; q < 4; q++) {
            const __half2* h2 = (const __half2*)vs[q];
            #pragma unroll
            for (int p = 0; p < 4; p++) {
                float2 f = __half22float2(h2[p]);
                acc[2 * p] += f.x; acc[2 * p + 1] += f.y;
            }
        }
    }
    for (; j < e; j++) {
        int r0 = adj[j];
        uint4 v0 = *(const uint4*)(src + (size_t)r0 * slda + t * 8);
        const __half2* h2 = (const __half2*)&v0;
        #pragma unroll
        for (int p = 0; p < 4; p++) {
            float2 f = __half22float2(h2[p]);
            acc[2 * p] += f.x; acc[2 * p + 1] += f.y;
        }
    }
    float inv = (e > s) ? 1.0f / (float)(e - s) : 0.0f;
    __half o8[8];
    #pragma unroll
    for (int q = 0; q < 8; q++) o8[q] = __float2half_rn(acc[q] * inv);
    *(uint4*)(dst + (size_t)n * dlda + coff + t * 8) = *(uint4*)&o8[0];
}

// ========== merged fp32->fp16 input conversion into A self slots ==========
__global__ void split2_kernel(const float* __restrict__ h_p, const float* __restrict__ h_d,
                              __half* __restrict__ Ap, __half* __restrict__ Ad) {
    size_t idx = (size_t)blockIdx.x * blockDim.x + threadIdx.x;
    if (idx >= (size_t)NNODE * FEAT) return;
    int row = (int)(idx >> 9), col = (int)(idx & 511);
    const float* src = blockIdx.y ? h_d : h_p;
    __half* A = blockIdx.y ? Ad : Ap;
    int lda = blockIdx.y ? 1024 : 2048;
    A[(size_t)row * lda + col] = __float2half_rn(src[idx]);
}

// ========== weight prep: tiled transpose + fuse + fp16 (also zeros g_cnt) ==========
__global__ void wprep_kernel(const float* __restrict__ Ws1, const float* __restrict__ Wn1,
                             const float* __restrict__ Ws2, const float* __restrict__ Wn2,
                             const float* __restrict__ pWd, const float* __restrict__ pWp) {
    {
        int bid = (blockIdx.z * 16 + blockIdx.y) * 16 + blockIdx.x;
        int id = bid * 1024 + threadIdx.y * 32 + threadIdx.x;
        if (id < 4 * NNODE) g_cnt[id] = 0;
    }
    __shared__ float tile[4][32][33];
    int which = blockIdx.z;
    int n0 = blockIdx.x * 32, k0 = blockIdx.y * 32;
    int tx = threadIdx.x, ty = threadIdx.y;
    int srcIdx = (k0 + ty) * 512 + (n0 + tx);
    int nslots;
    __half* B;
    int ldb;
    if (which == 0 || which == 2) {
        int li = which >> 1;
        const float* Ws = li ? Ws2 : Ws1;
        const float* Wn = li ? Wn2 : Wn1;
        tile[0][ty][tx] = Ws[srcIdx] + Ws[2 * FF + srcIdx] + Ws[3 * FF + srcIdx];
        tile[1][ty][tx] = Wn[srcIdx];
        tile[2][ty][tx] = Wn[2 * FF + srcIdx];
        tile[3][ty][tx] = Wn[3 * FF + srcIdx];
        nslots = 4; B = g_Bp[li]; ldb = 2048;
    } else if (which == 1 || which == 3) {
        int li = which >> 1;
        const float* Ws = li ? Ws2 : Ws1;
        const float* Wn = li ? Wn2 : Wn1;
        tile[0][ty][tx] = Ws[FF + srcIdx];
        tile[1][ty][tx] = Wn[FF + srcIdx];
        nslots = 2; B = g_Bd[li]; ldb = 1024;
    } else {
        int q = which - 4;
        const float* W = q ? pWp : pWd;
        tile[0][ty][tx] = W[srcIdx];
        nslots = 1; B = g_Bq[q]; ldb = 512;
    }
    __syncthreads();
    for (int sl = 0; sl < nslots; sl++) {
        float v = tile[sl][tx][ty];
        size_t o = (size_t)(n0 + ty) * ldb + sl * 512 + k0 + tx;
        B[o] = __float2half_rn(v);
    }
}
__global__ void bias_kernel(const float* __restrict__ b1, const float* __restrict__ b2) {
    int i = threadIdx.x;
    g_biasP[0][i] = b1[i] + b1[1024 + i] + b1[1536 + i];
    g_biasD[0][i] = b1[512 + i];
    g_biasP[1][i] = b2[i] + b2[1024 + i] + b2[1536 + i];
    g_biasD[1][i] = b2[512 + i];
}

// ================= paired tcgen05 fp16 GEMM, M=256 x N=256, KC=32, 4-stage pipeline =====
// C = A16 * B16 + bias (fp32 TMEM accum)
struct GPair {
    const __half *A0, *B0; const float* bias0; float* C0; int lda0, ldb0, K0;
    const __half *A1, *B1; const float* bias1; float* C1; int lda1, ldb1, K1;
};
#define STAGE_BYTES 32768   // A 16K | B 16K
#define GEMM_SMEM (1024 + 4 * STAGE_BYTES)
__global__ __launch_bounds__(128)
void mma_gemm_pair(const GPair gp, int M) {
    const __half* A   = blockIdx.z ? gp.A1 : gp.A0;
    const __half* B   = blockIdx.z ? gp.B1 : gp.B0;
    const float* bias = blockIdx.z ? gp.bias1 : gp.bias0;
    float* C = blockIdx.z ? gp.C1 : gp.C0;
    const int lda = blockIdx.z ? gp.lda1 : gp.lda0;
    const int ldb = blockIdx.z ? gp.ldb1 : gp.ldb0;
    const int Ktot = blockIdx.z ? gp.K1 : gp.K0;
#if HAS_TCGEN05
    extern __shared__ char smem[];
    uint32_t sb = smem_to_u32(smem);
    const int tid = threadIdx.x;
    const int wid = tid >> 5, lid = tid & 31;
    const int m0 = blockIdx.y * 256, n0 = blockIdx.x * 256;

    if (wid == 0) { TCGEN05_ALLOC(sb, 512); TCGEN05_RELINQ(); }
    if (tid == 0) MBARRIER_INIT(sb + 8, 1);
    __syncthreads();
    uint32_t tbase;
    asm volatile("ld.shared.b32 %0, [%1];" : "=r"(tbase) : "r"(sb));

    const uint32_t idesc = 0x8400010u;   // F32 acc, F16 A/B, M=128, N=256
    const int nst = Ktot >> 5;           // KC = 32

    auto issue_loads = [&](int s) {
        int k0 = s << 5;
        uint32_t base = sb + 1024 + (uint32_t)(s & 3) * STAGE_BYTES;
        // A: 256 rows x 64B = 1024 chunks; B: 256 rows x 64B = 1024 chunks; 8 each per thread
        #pragma unroll
        for (int c = 0; c < 8; c++) {
            int chunk = c * 128 + tid;
            int row = chunk >> 2, ch = chunk & 3;
            uint32_t sw = SMEM_SWIZZLE_64B((uint32_t)(row * 64 + ch * 16));
            size_t ga = (size_t)(m0 + row) * lda + k0 + ch * 8;
            size_t gb = (size_t)(n0 + row) * ldb + k0 + ch * 8;
            CP_ASYNC16(base + sw, A + ga);
            CP_ASYNC16(base + 16384 + sw, B + gb);
        }
        CP_COMMIT();
    };

    issue_loads(0);
    issue_loads(1);
    issue_loads(2);
    for (int s = 0; s < nst; s++) {
        if (s >= 1) MBARRIER_WAIT_PARITY(sb + 8, (s - 1) & 1);   // frees buffer (s-1)&3 for s+3
        if (s + 3 < nst)      { issue_loads(s + 3); CP_WAIT3(); }
        else if (s + 2 < nst) { CP_WAIT2(); }
        else if (s + 1 < nst) { CP_WAIT1(); }
        else                  { CP_WAIT0(); }
        __syncthreads();
        FENCE_ASYNC_SHARED();
        if (wid == 0 && elect_one_pred()) {
            uint32_t bufb = sb + 1024 + (uint32_t)(s & 3) * STAGE_BYTES;
            uint64_t dA0 = MAKE_SMEM_DESC64(bufb);
            uint64_t dA1 = MAKE_SMEM_DESC64(bufb + 8192);
            uint64_t dB  = MAKE_SMEM_DESC64(bufb + 16384);
            #pragma unroll
            for (int kk = 0; kk < 2; kk++) {
                uint64_t o = (uint64_t)(kk * 2);
                uint32_t en0 = !(s == 0 && kk == 0);
                mma_f16_ss(tbase,       dA0 + o, dB + o, idesc, en0);
                mma_f16_ss(tbase + 256, dA1 + o, dB + o, idesc, en0);
            }
            TCGEN05_COMMIT(sb + 8);
        }
    }
    MBARRIER_WAIT_PARITY(sb + 8, (nst - 1) & 1);
    TCGEN05_FENCE_AFTER();

    #pragma unroll
    for (int half = 0; half < 2; half++) {
        int gr = m0 + half * 128 + wid * 32 + lid;
        uint32_t dt = tbase + half * 256;
        #pragma unroll
        for (int base = 0; base < 256; base += 32) {
            uint32_t r[32];
            TCGEN05_LD_X32(r, dt + base);
            TCGEN05_WAIT_LD();
            if (gr < M) {
                float* cp = C + (size_t)gr * 512 + n0 + base;
                #pragma unroll
                for (int j = 0; j < 32; j += 4) {
                    float4 v;
                    v.x = __uint_as_float(r[j + 0]) + bias[n0 + base + j + 0];
                    v.y = __uint_as_float(r[j + 1]) + bias[n0 + base + j + 1];
                    v.z = __uint_as_float(r[j + 2]) + bias[n0 + base + j + 2];
                    v.w = __uint_as_float(r[j + 3]) + bias[n0 + base + j + 3];
                    *(float4*)(cp + j) = v;
                }
            }
        }
    }
    TCGEN05_FENCE_BEFORE();
    __syncthreads();
    if (tid == 0) MBARRIER_INVAL(sb + 8);
    __syncthreads();
    if (wid == 0) TCGEN05_DEALLOC(tbase, 512);
#else
    const int tid = threadIdx.x;
    const int m0 = blockIdx.y * 256, n0 = blockIdx.x * 256;
    for (int rc = tid; rc < 256 * 256; rc += blockDim.x) {
        int r = rc >> 8, c = rc & 255;
        int gr = m0 + r, gc = n0 + c;
        if (gr >= M) continue;
        const __half* a = A + (size_t)gr * lda;
        const __half* b = B + (size_t)gc * ldb;
        float acc = 0.f;
        for (int k = 0; k < Ktot; k++)
            acc += __half2float(a[k]) * __half2float(b[k]);
        C[(size_t)gr * 512 + gc] = acc + bias[gc];
    }
#endif
}

// ================= BatchNorm + ReLU (merged d+p) =================
__global__ void bn_reduce2_kernel(const float* __restrict__ xd, const float* __restrict__ xp) {
    int gcol = blockIdx.x * 256 + threadIdx.x;   // 0..1023
    int isP = gcol >= 512;
    int col = gcol & 511;
    const float* x = isP ? xp : xd;
    float s = 0.f, s2 = 0.f;
    for (int r = blockIdx.y; r < NNODE; r += gridDim.y) {
        float v = x[(size_t)r * FEAT + col];
        s += v; s2 += v * v;
    }
    int base = isP ? 1024 : 0;
    atomicAdd(&g_bnstat[base + col], s);
    atomicAdd(&g_bnstat[base + 512 + col], s2);
}
__global__ void bn_norm2_kernel(const float* __restrict__ rawd, const float* __restrict__ rawp,
                                __half* __restrict__ Ad, __half* __restrict__ Ap,
                                const float* __restrict__ gamma_l, const float* __restrict__ beta_l) {
    size_t idx = (size_t)blockIdx.x * blockDim.x + threadIdx.x;
    if (idx >= (size_t)NNODE * FEAT) return;
    int isP = blockIdx.y;
    int col = (int)(idx & (FEAT - 1));
    int row = (int)(idx >> 9);
    const float* raw = isP ? rawp : rawd;
    __half* Ax = isP ? Ap : Ad;
    int lda = isP ? 2048 : 1024;
    int sbase = isP ? 1024 : 0;
    const float* gamma = gamma_l + isP * FEAT;
    const float* beta  = beta_l + isP * FEAT;
    float mean = g_bnstat[sbase + col] * (1.0f / NNODE);
    float var  = g_bnstat[sbase + 512 + col] * (1.0f / NNODE) - mean * mean;
    float sc = gamma[col] * rsqrtf(var + BN_EPS);
    float v = (raw[idx] - mean) * sc + beta[col];
    v = v > 0.f ? v : 0.f;
    Ax[(size_t)row * lda + col] = __float2half_rn(v);
}

// ================= host orchestration =================
extern "C" void kernel_launch(void* const* d_in, const int* in_sizes, int n_in,
                              void* d_out, int out_size) {
    const float* h_d  = (const float*)d_in[0];
    const float* h_p  = (const float*)d_in[1];
    const float* Ws1  = (const float*)d_in[2];
    const float* Wn1  = (const float*)d_in[3];
    const float* b1   = (const float*)d_in[4];
    const float* Ws2  = (const float*)d_in[5];
    const float* Wn2  = (const float*)d_in[6];
    const float* b2   = (const float*)d_in[7];
    const float* gam  = (const float*)d_in[8];
    const float* bet  = (const float*)d_in[9];
    const float* pWd  = (const float*)d_in[10];
    const float* pbd  = (const float*)d_in[11];
    const float* pWp  = (const float*)d_in[12];
    const float* pbp  = (const float*)d_in[13];
    const int* a_src = (const int*)d_in[14];
    const int* a_dst = (const int*)d_in[15];
    const int* i_src = (const int*)d_in[16];
    const int* i_dst = (const int*)d_in[17];
    int E = in_sizes[14];

    float* out_d = (float*)d_out;
    float* out_p = out_d + (size_t)NNODE * FEAT;

    __half *Ap, *Ad, *Bp, *Bd, *Bq;
    float *rawd, *rawp, *biasP, *biasD;
    cudaGetSymbolAddress((void**)&Ap, g_Ap);
    cudaGetSymbolAddress((void**)&Ad, g_Ad);
    cudaGetSymbolAddress((void**)&Bp, g_Bp);
    cudaGetSymbolAddress((void**)&Bd, g_Bd);
    cudaGetSymbolAddress((void**)&Bq, g_Bq);
    cudaGetSymbolAddress((void**)&rawd, g_rawd);
    cudaGetSymbolAddress((void**)&rawp, g_rawp);
    cudaGetSymbolAddress((void**)&biasP, g_biasP);
    cudaGetSymbolAddress((void**)&biasD, g_biasD);

    cudaFuncSetAttribute(mma_gemm_pair, cudaFuncAttributeMaxDynamicSharedMemorySize, GEMM_SMEM);

    const int NW = (NNODE * FEAT + 255) / 256;
    const int MT = (NNODE + 255) / 256;               // 79
    const dim3 gpair(2, MT, 2);
    const dim3 g4(NNODE, 4);

    GPair lay[2];
    for (int li = 0; li < 2; li++) {
        lay[li].A0 = Ap; lay[li].B0 = Bp + (size_t)li * 512 * 2048;
        lay[li].bias0 = biasP + li * FEAT; lay[li].C0 = rawp;
        lay[li].lda0 = 2048; lay[li].ldb0 = 2048; lay[li].K0 = 2048;
        lay[li].A1 = Ad; lay[li].B1 = Bd + (size_t)li * 512 * 1024;
        lay[li].bias1 = biasD + li * FEAT; lay[li].C1 = rawd;
        lay[li].lda1 = 1024; lay[li].ldb1 = 1024; lay[li].K1 = 1024;
    }
    GPair proj;
    proj.A0 = Ad; proj.B0 = Bq;
    proj.bias0 = pbd; proj.C0 = out_d; proj.lda0 = 1024; proj.ldb0 = 512; proj.K0 = 512;
    proj.A1 = Ap; proj.B1 = Bq + FF;
    proj.bias1 = pbp; proj.C1 = out_p; proj.lda1 = 2048; proj.ldb1 = 512; proj.K1 = 512;

    // ---- prep (wprep also zeros g_cnt) ----
    wprep_kernel<<<dim3(16, 16, 6), dim3(32, 32)>>>(Ws1, Wn1, Ws2, Wn2, pWd, pWp);
    bias_kernel<<<1, 512>>>(b1, b2);
    split2_kernel<<<dim3(NW, 2), 256>>>(h_p, h_d, Ap, Ad);

    // ---- CSR build ----
    hist_kernel<<<(4 * E + 255) / 256, 256>>>(a_src, a_dst, i_src, i_dst, E);
    scan_kernel<<<4, 1024>>>();
    fill_kernel<<<(4 * E + 255) / 256, 256>>>(a_src, a_dst, i_src, i_dst, E);

    // ---- layers ----
    for (int li = 0; li < 2; li++) {
        gather4_kernel<<<g4, 64>>>(Ad, Ap, E);   // also zeros g_bnstat
        mma_gemm_pair<<<gpair, 128, GEMM_SMEM>>>(lay[li], NNODE);
        bn_reduce2_kernel<<<dim3(4, 64), 256>>>(rawd, rawp);
        bn_norm2_kernel<<<dim3(NW, 2), 256>>>(rawd, rawp, Ad, Ap,
                                              gam + li * 2 * FEAT, bet + li * 2 * FEAT);
    }

    // ---- projections ----
    mma_gemm_pair<<<gpair, 128, GEMM_SMEM>>>(proj, NNODE);
}

// round 15
// speedup vs baseline: 2.0104x; 1.2388x over previous
#include <cuda_runtime.h>
#include <cuda_bf16.h>
#include <cuda_fp16.h>
#include <cstdint>

#define NNODE 20000
#define MPAD  20480
#define FEAT  512
#define EMAX  320000
#define FF    (FEAT*FEAT)
#define BN_EPS 1e-5f

#if defined(__CUDA_ARCH_FEAT_SM103_ALL) || defined(__CUDA_ARCH_FEAT_SM100_ALL) || defined(__CUDA_ARCH_FEAT_SM101_ALL)
#define HAS_TCGEN05 1
#else
#define HAS_TCGEN05 0
#endif

// ================= device scratch (static, no allocs) =================
__device__ __half g_Ap[(size_t)MPAD * 2048];   // self slot [0,512) = gather source
__device__ __half g_Ad[(size_t)MPAD * 1024];
__device__ __half g_Bp[2][512 * 2048];         // single fp16 weights (transposed, fused)
__device__ __half g_Bd[2][512 * 1024];
__device__ __half g_Bq[2][512 * 512];
__device__ float g_biasP[2][FEAT];
__device__ float g_biasD[2][FEAT];
__device__ float g_rawd[(size_t)NNODE * FEAT];
__device__ float g_rawp[(size_t)NNODE * FEAT];
__device__ float g_bnstat[4 * FEAT];   // [d_sum, d_sq, p_sum, p_sq]
__device__ int   g_cnt[4 * NNODE];
__device__ int   g_cur[4 * NNODE];
__device__ int   g_off[4 * (NNODE + 1)];
__device__ int   g_adj[4 * EMAX];

// ================= PTX helpers =================
__device__ __forceinline__ uint32_t smem_to_u32(const void* p) {
    uint32_t a;
    asm("{ .reg .u64 t; cvta.to.shared.u64 t, %1; cvt.u32.u64 %0, t; }" : "=r"(a) : "l"(p));
    return a;
}
__device__ __forceinline__ uint32_t elect_one_pred() {
    uint32_t pred;
    asm volatile("{\n\t.reg .pred p;\n\telect.sync _|p, 0xFFFFFFFF;\n\tselp.b32 %0, 1, 0, p;\n\t}" : "=r"(pred));
    return pred;
}
#define SMEM_SWIZZLE_64B(o) ((o) ^ (((o) >> 3) & 0x30))
static constexpr uint64_t SMEM_DESC_BASE_SW64 =
    (uint64_t(4) << 61) | (uint64_t(1) << 46) | (uint64_t(32) << 32) | (uint64_t(1) << 16);
#define MAKE_SMEM_DESC64(base) (SMEM_DESC_BASE_SW64 | ((uint64_t)((base) >> 4) & 0x3FFF))

#define CP_ASYNC16(dst, src) \
    asm volatile("cp.async.cg.shared.global [%0], [%1], 16;" :: "r"(dst), "l"(src) : "memory")
#define CP_COMMIT() asm volatile("cp.async.commit_group;" ::: "memory")
#define CP_WAIT3() asm volatile("cp.async.wait_group 3;" ::: "memory")
#define CP_WAIT2() asm volatile("cp.async.wait_group 2;" ::: "memory")
#define CP_WAIT1() asm volatile("cp.async.wait_group 1;" ::: "memory")
#define CP_WAIT0() asm volatile("cp.async.wait_group 0;" ::: "memory")

#if HAS_TCGEN05
#define TCGEN05_ALLOC(sm, n) \
    asm volatile("tcgen05.alloc.cta_group::1.sync.aligned.shared::cta.b32 [%0], %1;" \
                 :: "r"((uint32_t)(sm)), "r"((uint32_t)(n)) : "memory")
#define TCGEN05_DEALLOC(t, n) \
    asm volatile("tcgen05.dealloc.cta_group::1.sync.aligned.b32 %0, %1;" :: "r"(t), "r"((uint32_t)(n)))
#define TCGEN05_RELINQ() \
    asm volatile("tcgen05.relinquish_alloc_permit.cta_group::1.sync.aligned;")
#define TCGEN05_COMMIT(mb) \
    asm volatile("tcgen05.commit.cta_group::1.mbarrier::arrive::one.shared::cluster.b64 [%0];" \
                 :: "r"((uint32_t)(mb)) : "memory")
#define TCGEN05_WAIT_LD()  asm volatile("tcgen05.wait::ld.sync.aligned;" ::: "memory")
#define TCGEN05_FENCE_BEFORE() asm volatile("tcgen05.fence::before_thread_sync;" ::: "memory")
#define TCGEN05_FENCE_AFTER()  asm volatile("tcgen05.fence::after_thread_sync;" ::: "memory")
#define FENCE_ASYNC_SHARED() asm volatile("fence.proxy.async.shared::cta;" ::: "memory")
#define MBARRIER_INIT(mb, c) \
    asm volatile("mbarrier.init.shared.b64 [%0], %1;" :: "r"((uint32_t)(mb)), "r"((uint32_t)(c)) : "memory")
#define MBARRIER_INVAL(mb) \
    asm volatile("mbarrier.inval.shared.b64 [%0];" :: "r"((uint32_t)(mb)) : "memory")
#define MBARRIER_WAIT_PARITY(mb, ph) do { \
    uint32_t _mb = (uint32_t)(mb), _ph = (uint32_t)(ph), _done; \
    asm volatile("{\n\t.reg .pred p;\n\tmbarrier.try_wait.parity.acquire.cta.shared::cta.b64 p, [%1], %2;\n\tselp.b32 %0, 1, 0, p;\n\t}" \
        : "=r"(_done) : "r"(_mb), "r"(_ph) : "memory"); \
    if (!_done) { \
        asm volatile("{\n\t.reg .pred P1;\n\tWL_%=: \n\tmbarrier.try_wait.parity.acquire.cta.shared::cta.b64 P1, [%0], %1, 0x989680;\n\t@P1 bra.uni WD_%=;\n\tbra.uni WL_%=;\n\tWD_%=: \n\t}" \
            :: "r"(_mb), "r"(_ph) : "memory"); \
    } \
} while (0)

#define TCGEN05_LD_X32(r, addr) \
    asm volatile("tcgen05.ld.sync.aligned.32x32b.x32.b32 " \
        "{%0, %1, %2, %3, %4, %5, %6, %7, %8, %9, %10, %11, %12, %13, %14, %15, " \
        " %16, %17, %18, %19, %20, %21, %22, %23, %24, %25, %26, %27, %28, %29, %30, %31}, [%32];" \
        : "=r"((r)[0]), "=r"((r)[1]), "=r"((r)[2]), "=r"((r)[3]), "=r"((r)[4]), "=r"((r)[5]), "=r"((r)[6]), "=r"((r)[7]), \
          "=r"((r)[8]), "=r"((r)[9]), "=r"((r)[10]), "=r"((r)[11]), "=r"((r)[12]), "=r"((r)[13]), "=r"((r)[14]), "=r"((r)[15]), \
          "=r"((r)[16]), "=r"((r)[17]), "=r"((r)[18]), "=r"((r)[19]), "=r"((r)[20]), "=r"((r)[21]), "=r"((r)[22]), "=r"((r)[23]), \
          "=r"((r)[24]), "=r"((r)[25]), "=r"((r)[26]), "=r"((r)[27]), "=r"((r)[28]), "=r"((r)[29]), "=r"((r)[30]), "=r"((r)[31]) \
        : "r"(addr))

__device__ __forceinline__ void mma_f16_ss(uint32_t d_tmem, uint64_t a_desc, uint64_t b_desc,
                                           uint32_t idesc, uint32_t enable) {
    asm volatile(
        "{\n\t.reg .pred p;\n\tsetp.ne.u32 p, %5, 0;\n\t"
        "tcgen05.mma.cta_group::1.kind::f16 [%0], %1, %2, %3, {%4, %4, %4, %4}, p;\n\t}"
        :: "r"(d_tmem), "l"(a_desc), "l"(b_desc), "r"(idesc), "r"(0u), "r"(enable)
        : "memory");
}
#endif // HAS_TCGEN05

// ================= CSR build =================
__global__ void hist_kernel(const int* __restrict__ a_src, const int* __restrict__ a_dst,
                            const int* __restrict__ i_src, const int* __restrict__ i_dst, int E) {
    int i = blockIdx.x * blockDim.x + threadIdx.x;
    if (i >= 4 * E) return;
    int w = i / E, e = i - w * E;
    int k = (w == 0) ? a_dst[e] : (w == 1) ? a_src[e] : (w == 2) ? i_dst[e] : i_src[e];
    atomicAdd(&g_cnt[w * NNODE + k], 1);
}
__global__ void scan_kernel() {
    int c = blockIdx.x;
    __shared__ int sh[1024];
    __shared__ int carry_sh;
    int tid = threadIdx.x;
    if (tid == 0) { carry_sh = 0; g_off[c * (NNODE + 1)] = 0; }
    __syncthreads();
    for (int base = 0; base < NNODE; base += 1024) {
        int i = base + tid;
        int v = (i < NNODE) ? g_cnt[c * NNODE + i] : 0;
        sh[tid] = v;
        __syncthreads();
        #pragma unroll
        for (int d = 1; d < 1024; d <<= 1) {
            int t = (tid >= d) ? sh[tid - d] : 0;
            __syncthreads();
            sh[tid] += t;
            __syncthreads();
        }
        int incl = sh[tid];
        int carry = carry_sh;
        __syncthreads();
        if (i < NNODE) {
            g_off[c * (NNODE + 1) + i + 1] = carry + incl;
            g_cur[c * NNODE + i] = carry + incl - v;
        }
        if (tid == 1023) carry_sh = carry + sh[1023];
        __syncthreads();
    }
}
__global__ void fill_kernel(const int* __restrict__ a_src, const int* __restrict__ a_dst,
                            const int* __restrict__ i_src, const int* __restrict__ i_dst, int E) {
    int i = blockIdx.x * blockDim.x + threadIdx.x;
    if (i >= 4 * E) return;
    int w = i / E, e = i - w * E;
    int k = (w == 0) ? a_dst[e] : (w == 1) ? a_src[e] : (w == 2) ? i_dst[e] : i_src[e];
    int v = (w == 0) ? a_src[e] : (w == 1) ? a_dst[e] : (w == 2) ? i_src[e] : i_dst[e];
    int pos = atomicAdd(&g_cur[w * NNODE + k], 1);
    g_adj[w * E + pos] = v;
}

// ========== fused 4-way segment-mean gather (also zeros BN stats for this layer) ==========
__global__ void gather4_kernel(const __half* __restrict__ Ad, __half* __restrict__ Ap, int E) {
    if (blockIdx.y == 0 && blockIdx.x < 32) {
        int z = blockIdx.x * 64 + threadIdx.x;
        if (z < 4 * FEAT) g_bnstat[z] = 0.f;
    }
    int c = blockIdx.y;
    const __half* src;
    __half* dst;
    int slda, dlda, coff;
    if (c == 0) { src = Ad; slda = 1024; dst = Ap; dlda = 2048; coff = 512; }
    else if (c == 1) { src = Ap; slda = 2048; dst = (__half*)Ad; dlda = 1024; coff = 512; }
    else { src = Ap; slda = 2048; dst = Ap; dlda = 2048; coff = (c == 2) ? 1024 : 1536; }
    int n = blockIdx.x;
    int t = threadIdx.x;            // 0..63, 8 halves each (16B)
    int s = g_off[c * (NNODE + 1) + n];
    int e = g_off[c * (NNODE + 1) + n + 1];
    const int* adj = g_adj + (size_t)c * E;
    float acc[8] = {0.f, 0.f, 0.f, 0.f, 0.f, 0.f, 0.f, 0.f};
    int j = s;
    for (; j + 3 < e; j += 4) {
        int r0 = adj[j], r1 = adj[j + 1], r2 = adj[j + 2], r3 = adj[j + 3];
        uint4 v0 = *(const uint4*)(src + (size_t)r0 * slda + t * 8);
        uint4 v1 = *(const uint4*)(src + (size_t)r1 * slda + t * 8);
        uint4 v2 = *(const uint4*)(src + (size_t)r2 * slda + t * 8);
        uint4 v3 = *(const uint4*)(src + (size_t)r3 * slda + t * 8);
        const uint4* vs[4] = {&v0, &v1, &v2, &v3};
        #pragma unroll
        for (int q = 0; q < 4; q++) {
            const __half2* h2 = (const __half2*)vs[q];
            #pragma unroll
            for (int p = 0; p < 4; p++) {
                float2 f = __half22float2(h2[p]);
                acc[2 * p] += f.x; acc[2 * p + 1] += f.y;
            }
        }
    }
    for (; j < e; j++) {
        int r0 = adj[j];
        uint4 v0 = *(const uint4*)(src + (size_t)r0 * slda + t * 8);
        const __half2* h2 = (const __half2*)&v0;
        #pragma unroll
        for (int p = 0; p < 4; p++) {
            float2 f = __half22float2(h2[p]);
            acc[2 * p] += f.x; acc[2 * p + 1] += f.y;
        }
    }
    float inv = (e > s) ? 1.0f / (float)(e - s) : 0.0f;
    __half o8[8];
    #pragma unroll
    for (int q = 0; q < 8; q++) o8[q] = __float2half_rn(acc[q] * inv);
    *(uint4*)(dst + (size_t)n * dlda + coff + t * 8) = *(uint4*)&o8[0];
}

// ========== mega prep: split2 + wprep + zero_cnt + bias in ONE launch ==========
// flat grid: [0,20000) split quads | [20000,21536) wprep tiles | [21536,21849) zero | [21849,21851) bias
#define MP_SPLIT 20000
#define MP_WPREP 1536
#define MP_ZERO  313
#define MP_TOTAL (MP_SPLIT + MP_WPREP + MP_ZERO + 2)
__global__ void mega_prep_kernel(const float* __restrict__ h_p, const float* __restrict__ h_d,
                                 __half* __restrict__ Ap, __half* __restrict__ Ad,
                                 const float* __restrict__ Ws1, const float* __restrict__ Wn1,
                                 const float* __restrict__ Ws2, const float* __restrict__ Wn2,
                                 const float* __restrict__ pWd, const float* __restrict__ pWp,
                                 const float* __restrict__ b1, const float* __restrict__ b2) {
    int b = blockIdx.x;
    int tid = threadIdx.x;
    if (b < MP_SPLIT) {
        // input fp32 -> fp16 into A self slots; 4 elems/thread, 1024 elems/block
        // first 10000 blocks: protein; next 10000: disease
        int isD = b >= 10000;
        size_t e0 = ((size_t)(isD ? b - 10000 : b) * 256 + tid) * 4;   // element index
        const float* src = isD ? h_d : h_p;
        __half* A = isD ? Ad : Ap;
        int lda = isD ? 1024 : 2048;
        float4 v = *(const float4*)(src + e0);
        int row = (int)(e0 >> 9), col = (int)(e0 & 511);
        __half h4[4] = {__float2half_rn(v.x), __float2half_rn(v.y),
                        __float2half_rn(v.z), __float2half_rn(v.w)};
        *(uint2*)(A + (size_t)row * lda + col) = *(uint2*)&h4[0];
    } else if (b < MP_SPLIT + MP_WPREP) {
        // weight transpose+fuse+fp16; one 32x32 tile per block, 256 threads (8 rows/pass)
        int wb = b - MP_SPLIT;
        int which = wb >> 8;             // 0..5
        int rem = wb & 255;
        int n0 = (rem & 15) * 32, k0 = (rem >> 4) * 32;
        int tx = tid & 31, ty = tid >> 5;   // ty 0..7
        __shared__ float tile[4][32][33];
        int nslots;
        __half* B;
        int ldb;
        const float *Ws = nullptr, *Wn = nullptr, *W = nullptr;
        if (which == 0 || which == 2) {
            int li = which >> 1;
            Ws = li ? Ws2 : Ws1; Wn = li ? Wn2 : Wn1;
            nslots = 4; B = g_Bp[li]; ldb = 2048;
        } else if (which == 1 || which == 3) {
            int li = which >> 1;
            Ws = li ? Ws2 : Ws1; Wn = li ? Wn2 : Wn1;
            nslots = 2; B = g_Bd[li]; ldb = 1024;
        } else {
            int q = which - 4;
            W = q ? pWp : pWd;
            nslots = 1; B = g_Bq[q]; ldb = 512;
        }
        #pragma unroll
        for (int r = 0; r < 4; r++) {
            int yy = r * 8 + ty;
            int srcIdx = (k0 + yy) * 512 + (n0 + tx);
            if (which == 0 || which == 2) {
                tile[0][yy][tx] = Ws[srcIdx] + Ws[2 * FF + srcIdx] + Ws[3 * FF + srcIdx];
                tile[1][yy][tx] = Wn[srcIdx];
                tile[2][yy][tx] = Wn[2 * FF + srcIdx];
                tile[3][yy][tx] = Wn[3 * FF + srcIdx];
            } else if (which == 1 || which == 3) {
                tile[0][yy][tx] = Ws[FF + srcIdx];
                tile[1][yy][tx] = Wn[FF + srcIdx];
            } else {
                tile[0][yy][tx] = W[srcIdx];
            }
        }
        __syncthreads();
        #pragma unroll
        for (int r = 0; r < 4; r++) {
            int yy = r * 8 + ty;
            for (int sl = 0; sl < nslots; sl++) {
                float v = tile[sl][tx][yy];
                size_t o = (size_t)(n0 + yy) * ldb + sl * 512 + k0 + tx;
                B[o] = __float2half_rn(v);
            }
        }
    } else if (b < MP_SPLIT + MP_WPREP + MP_ZERO) {
        int id = (b - MP_SPLIT - MP_WPREP) * 256 + tid;
        if (id < 4 * NNODE) g_cnt[id] = 0;
    } else {
        int half = b - MP_SPLIT - MP_WPREP - MP_ZERO;   // 0 or 1
        int i = half * 256 + tid;
        g_biasP[0][i] = b1[i] + b1[1024 + i] + b1[1536 + i];
        g_biasD[0][i] = b1[512 + i];
        g_biasP[1][i] = b2[i] + b2[1024 + i] + b2[1536 + i];
        g_biasD[1][i] = b2[512 + i];
    }
}

// ================= paired tcgen05 fp16 GEMM, M=128 x N=256, KC=32, 4-stage, 2 CTA/SM ====
// C = A16 * B16 + bias (fp32 TMEM accum, 256 TMEM cols per CTA)
struct GPair {
    const __half *A0, *B0; const float* bias0; float* C0; int lda0, ldb0, K0;
    const __half *A1, *B1; const float* bias1; float* C1; int lda1, ldb1, K1;
};
#define STAGE_BYTES 24576   // A 8K | B 16K
#define GEMM_SMEM (1024 + 4 * STAGE_BYTES)   // 99,328 B -> 2 CTAs/SM
__global__ __launch_bounds__(128)
void mma_gemm_pair(const GPair gp, int M) {
    const __half* A   = blockIdx.z ? gp.A1 : gp.A0;
    const __half* B   = blockIdx.z ? gp.B1 : gp.B0;
    const float* bias = blockIdx.z ? gp.bias1 : gp.bias0;
    float* C = blockIdx.z ? gp.C1 : gp.C0;
    const int lda = blockIdx.z ? gp.lda1 : gp.lda0;
    const int ldb = blockIdx.z ? gp.ldb1 : gp.ldb0;
    const int Ktot = blockIdx.z ? gp.K1 : gp.K0;
#if HAS_TCGEN05
    extern __shared__ char smem[];
    uint32_t sb = smem_to_u32(smem);
    const int tid = threadIdx.x;
    const int wid = tid >> 5, lid = tid & 31;
    const int m0 = blockIdx.y * 128, n0 = blockIdx.x * 256;

    if (wid == 0) { TCGEN05_ALLOC(sb, 256); TCGEN05_RELINQ(); }
    if (tid == 0) MBARRIER_INIT(sb + 8, 1);
    __syncthreads();
    uint32_t tbase;
    asm volatile("ld.shared.b32 %0, [%1];" : "=r"(tbase) : "r"(sb));

    const uint32_t idesc = 0x8400010u;   // F32 acc, F16 A/B, M=128, N=256
    const int nst = Ktot >> 5;           // KC = 32

    auto issue_loads = [&](int s) {
        int k0 = s << 5;
        uint32_t base = sb + 1024 + (uint32_t)(s & 3) * STAGE_BYTES;
        #pragma unroll
        for (int c = 0; c < 4; c++) {
            int chunk = c * 128 + tid;
            int row = chunk >> 2, ch = chunk & 3;
            uint32_t sw = SMEM_SWIZZLE_64B((uint32_t)(row * 64 + ch * 16));
            size_t ga = (size_t)(m0 + row) * lda + k0 + ch * 8;
            CP_ASYNC16(base + sw, A + ga);
        }
        #pragma unroll
        for (int c = 0; c < 8; c++) {
            int chunk = c * 128 + tid;
            int row = chunk >> 2, ch = chunk & 3;
            uint32_t sw = SMEM_SWIZZLE_64B((uint32_t)(row * 64 + ch * 16));
            size_t gb = (size_t)(n0 + row) * ldb + k0 + ch * 8;
            CP_ASYNC16(base + 8192 + sw, B + gb);
        }
        CP_COMMIT();
    };

    issue_loads(0);
    issue_loads(1);
    issue_loads(2);
    for (int s = 0; s < nst; s++) {
        if (s >= 1) MBARRIER_WAIT_PARITY(sb + 8, (s - 1) & 1);
        if (s + 3 < nst)      { issue_loads(s + 3); CP_WAIT3(); }
        else if (s + 2 < nst) { CP_WAIT2(); }
        else if (s + 1 < nst) { CP_WAIT1(); }
        else                  { CP_WAIT0(); }
        __syncthreads();
        FENCE_ASYNC_SHARED();
        if (wid == 0 && elect_one_pred()) {
            uint32_t bufb = sb + 1024 + (uint32_t)(s & 3) * STAGE_BYTES;
            uint64_t dA = MAKE_SMEM_DESC64(bufb);
            uint64_t dB = MAKE_SMEM_DESC64(bufb + 8192);
            #pragma unroll
            for (int kk = 0; kk < 2; kk++) {
                uint64_t o = (uint64_t)(kk * 2);
                mma_f16_ss(tbase, dA + o, dB + o, idesc, !(s == 0 && kk == 0));
            }
            TCGEN05_COMMIT(sb + 8);
        }
    }
    MBARRIER_WAIT_PARITY(sb + 8, (nst - 1) & 1);
    TCGEN05_FENCE_AFTER();

    int gr = m0 + wid * 32 + lid;
    #pragma unroll
    for (int base = 0; base < 256; base += 32) {
        uint32_t r[32];
        TCGEN05_LD_X32(r, tbase + base);
        TCGEN05_WAIT_LD();
        if (gr < M) {
            float* cp = C + (size_t)gr * 512 + n0 + base;
            #pragma unroll
            for (int j = 0; j < 32; j += 4) {
                float4 v;
                v.x = __uint_as_float(r[j + 0]) + bias[n0 + base + j + 0];
                v.y = __uint_as_float(r[j + 1]) + bias[n0 + base + j + 1];
                v.z = __uint_as_float(r[j + 2]) + bias[n0 + base + j + 2];
                v.w = __uint_as_float(r[j + 3]) + bias[n0 + base + j + 3];
                *(float4*)(cp + j) = v;
            }
        }
    }
    TCGEN05_FENCE_BEFORE();
    __syncthreads();
    if (tid == 0) MBARRIER_INVAL(sb + 8);
    __syncthreads();
    if (wid == 0) TCGEN05_DEALLOC(tbase, 256);
#else
    const int tid = threadIdx.x;
    const int m0 = blockIdx.y * 128, n0 = blockIdx.x * 256;
    for (int rc = tid; rc < 128 * 256; rc += blockDim.x) {
        int r = rc >> 8, c = rc & 255;
        int gr = m0 + r, gc = n0 + c;
        if (gr >= M) continue;
        const __half* a = A + (size_t)gr * lda;
        const __half* b = B + (size_t)gc * ldb;
        float acc = 0.f;
        for (int k = 0; k < Ktot; k++)
            acc += __half2float(a[k]) * __half2float(b[k]);
        C[(size_t)gr * 512 + gc] = acc + bias[gc];
    }
#endif
}

// ================= BatchNorm + ReLU (merged d+p) =================
__global__ void bn_reduce2_kernel(const float* __restrict__ xd, const float* __restrict__ xp) {
    int gcol = blockIdx.x * 256 + threadIdx.x;   // 0..1023
    int isP = gcol >= 512;
    int col = gcol & 511;
    const float* x = isP ? xp : xd;
    float s = 0.f, s2 = 0.f;
    for (int r = blockIdx.y; r < NNODE; r += gridDim.y) {
        float v = x[(size_t)r * FEAT + col];
        s += v; s2 += v * v;
    }
    int base = isP ? 1024 : 0;
    atomicAdd(&g_bnstat[base + col], s);
    atomicAdd(&g_bnstat[base + 512 + col], s2);
}
__global__ void bn_norm2_kernel(const float* __restrict__ rawd, const float* __restrict__ rawp,
                                __half* __restrict__ Ad, __half* __restrict__ Ap,
                                const float* __restrict__ gamma_l, const float* __restrict__ beta_l) {
    size_t idx = (size_t)blockIdx.x * blockDim.x + threadIdx.x;
    if (idx >= (size_t)NNODE * FEAT) return;
    int isP = blockIdx.y;
    int col = (int)(idx & (FEAT - 1));
    int row = (int)(idx >> 9);
    const float* raw = isP ? rawp : rawd;
    __half* Ax = isP ? Ap : Ad;
    int lda = isP ? 2048 : 1024;
    int sbase = isP ? 1024 : 0;
    const float* gamma = gamma_l + isP * FEAT;
    const float* beta  = beta_l + isP * FEAT;
    float mean = g_bnstat[sbase + col] * (1.0f / NNODE);
    float var  = g_bnstat[sbase + 512 + col] * (1.0f / NNODE) - mean * mean;
    float sc = gamma[col] * rsqrtf(var + BN_EPS);
    float v = (raw[idx] - mean) * sc + beta[col];
    v = v > 0.f ? v : 0.f;
    Ax[(size_t)row * lda + col] = __float2half_rn(v);
}

// ================= host orchestration =================
extern "C" void kernel_launch(void* const* d_in, const int* in_sizes, int n_in,
                              void* d_out, int out_size) {
    const float* h_d  = (const float*)d_in[0];
    const float* h_p  = (const float*)d_in[1];
    const float* Ws1  = (const float*)d_in[2];
    const float* Wn1  = (const float*)d_in[3];
    const float* b1   = (const float*)d_in[4];
    const float* Ws2  = (const float*)d_in[5];
    const float* Wn2  = (const float*)d_in[6];
    const float* b2   = (const float*)d_in[7];
    const float* gam  = (const float*)d_in[8];
    const float* bet  = (const float*)d_in[9];
    const float* pWd  = (const float*)d_in[10];
    const float* pbd  = (const float*)d_in[11];
    const float* pWp  = (const float*)d_in[12];
    const float* pbp  = (const float*)d_in[13];
    const int* a_src = (const int*)d_in[14];
    const int* a_dst = (const int*)d_in[15];
    const int* i_src = (const int*)d_in[16];
    const int* i_dst = (const int*)d_in[17];
    int E = in_sizes[14];

    float* out_d = (float*)d_out;
    float* out_p = out_d + (size_t)NNODE * FEAT;

    __half *Ap, *Ad, *Bp, *Bd, *Bq;
    float *rawd, *rawp, *biasP, *biasD;
    cudaGetSymbolAddress((void**)&Ap, g_Ap);
    cudaGetSymbolAddress((void**)&Ad, g_Ad);
    cudaGetSymbolAddress((void**)&Bp, g_Bp);
    cudaGetSymbolAddress((void**)&Bd, g_Bd);
    cudaGetSymbolAddress((void**)&Bq, g_Bq);
    cudaGetSymbolAddress((void**)&rawd, g_rawd);
    cudaGetSymbolAddress((void**)&rawp, g_rawp);
    cudaGetSymbolAddress((void**)&biasP, g_biasP);
    cudaGetSymbolAddress((void**)&biasD, g_biasD);

    cudaFuncSetAttribute(mma_gemm_pair, cudaFuncAttributeMaxDynamicSharedMemorySize, GEMM_SMEM);

    const int NW = (NNODE * FEAT + 255) / 256;
    const int MT = (NNODE + 127) / 128;               // 157
    const dim3 gpair(2, MT, 2);
    const dim3 g4(NNODE, 4);

    GPair lay[2];
    for (int li = 0; li < 2; li++) {
        lay[li].A0 = Ap; lay[li].B0 = Bp + (size_t)li * 512 * 2048;
        lay[li].bias0 = biasP + li * FEAT; lay[li].C0 = rawp;
        lay[li].lda0 = 2048; lay[li].ldb0 = 2048; lay[li].K0 = 2048;
        lay[li].A1 = Ad; lay[li].B1 = Bd + (size_t)li * 512 * 1024;
        lay[li].bias1 = biasD + li * FEAT; lay[li].C1 = rawd;
        lay[li].lda1 = 1024; lay[li].ldb1 = 1024; lay[li].K1 = 1024;
    }
    GPair proj;
    proj.A0 = Ad; proj.B0 = Bq;
    proj.bias0 = pbd; proj.C0 = out_d; proj.lda0 = 1024; proj.ldb0 = 512; proj.K0 = 512;
    proj.A1 = Ap; proj.B1 = Bq + FF;
    proj.bias1 = pbp; proj.C1 = out_p; proj.lda1 = 2048; proj.ldb1 = 512; proj.K1 = 512;

    // ---- fused prep: split2 + wprep + zero_cnt + bias in one launch ----
    mega_prep_kernel<<<MP_TOTAL, 256>>>(h_p, h_d, Ap, Ad,
                                        Ws1, Wn1, Ws2, Wn2, pWd, pWp, b1, b2);

    // ---- CSR build ----
    hist_kernel<<<(4 * E + 255) / 256, 256>>>(a_src, a_dst, i_src, i_dst, E);
    scan_kernel<<<4, 1024>>>();
    fill_kernel<<<(4 * E + 255) / 256, 256>>>(a_src, a_dst, i_src, i_dst, E);

    // ---- layers ----
    for (int li = 0; li < 2; li++) {
        gather4_kernel<<<g4, 64>>>(Ad, Ap, E);   // also zeros g_bnstat
        mma_gemm_pair<<<gpair, 128, GEMM_SMEM>>>(lay[li], NNODE);
        bn_reduce2_kernel<<<dim3(4, 64), 256>>>(rawd, rawp);
        bn_norm2_kernel<<<dim3(NW, 2), 256>>>(rawd, rawp, Ad, Ap,
                                              gam + li * 2 * FEAT, bet + li * 2 * FEAT);
    }

    // ---- projections ----
    mma_gemm_pair<<<gpair, 128, GEMM_SMEM>>>(proj, NNODE);
}

// round 16
// speedup vs baseline: 2.0372x; 1.0134x over previous
#include <cuda_runtime.h>
#include <cuda_bf16.h>
#include <cuda_fp16.h>
#include <cstdint>

#define NNODE 20000
#define MPAD  20480
#define FEAT  512
#define EMAX  320000
#define FF    (FEAT*FEAT)
#define BN_EPS 1e-5f

#if defined(__CUDA_ARCH_FEAT_SM103_ALL) || defined(__CUDA_ARCH_FEAT_SM100_ALL) || defined(__CUDA_ARCH_FEAT_SM101_ALL)
#define HAS_TCGEN05 1
#else
#define HAS_TCGEN05 0
#endif

// ================= device scratch (static, no allocs) =================
__device__ __half g_Ap[(size_t)MPAD * 2048];   // self slot [0,512) = gather source
__device__ __half g_Ad[(size_t)MPAD * 1024];
__device__ __half g_Bp[2][512 * 2048];         // single fp16 weights (transposed, fused)
__device__ __half g_Bd[2][512 * 1024];
__device__ __half g_Bq[2][512 * 512];
__device__ float g_biasP[2][FEAT];
__device__ float g_biasD[2][FEAT];
__device__ float g_rawd[(size_t)NNODE * FEAT];
__device__ float g_rawp[(size_t)NNODE * FEAT];
__device__ float g_bnstat[4 * FEAT];   // [d_sum, d_sq, p_sum, p_sq]
__device__ int   g_cnt[4 * NNODE];
__device__ int   g_cur[4 * NNODE];
__device__ int   g_off[4 * (NNODE + 1)];
__device__ int   g_adj[4 * EMAX];

// ================= PTX helpers =================
__device__ __forceinline__ uint32_t smem_to_u32(const void* p) {
    uint32_t a;
    asm("{ .reg .u64 t; cvta.to.shared.u64 t, %1; cvt.u32.u64 %0, t; }" : "=r"(a) : "l"(p));
    return a;
}
__device__ __forceinline__ uint32_t elect_one_pred() {
    uint32_t pred;
    asm volatile("{\n\t.reg .pred p;\n\telect.sync _|p, 0xFFFFFFFF;\n\tselp.b32 %0, 1, 0, p;\n\t}" : "=r"(pred));
    return pred;
}
#define SMEM_SWIZZLE_64B(o) ((o) ^ (((o) >> 3) & 0x30))
static constexpr uint64_t SMEM_DESC_BASE_SW64 =
    (uint64_t(4) << 61) | (uint64_t(1) << 46) | (uint64_t(32) << 32) | (uint64_t(1) << 16);
#define MAKE_SMEM_DESC64(base) (SMEM_DESC_BASE_SW64 | ((uint64_t)((base) >> 4) & 0x3FFF))

#define CP_ASYNC16(dst, src) \
    asm volatile("cp.async.cg.shared.global [%0], [%1], 16;" :: "r"(dst), "l"(src) : "memory")
#define CP_COMMIT() asm volatile("cp.async.commit_group;" ::: "memory")
#define CP_WAIT3() asm volatile("cp.async.wait_group 3;" ::: "memory")
#define CP_WAIT2() asm volatile("cp.async.wait_group 2;" ::: "memory")
#define CP_WAIT1() asm volatile("cp.async.wait_group 1;" ::: "memory")
#define CP_WAIT0() asm volatile("cp.async.wait_group 0;" ::: "memory")

#if HAS_TCGEN05
#define TCGEN05_ALLOC(sm, n) \
    asm volatile("tcgen05.alloc.cta_group::1.sync.aligned.shared::cta.b32 [%0], %1;" \
                 :: "r"((uint32_t)(sm)), "r"((uint32_t)(n)) : "memory")
#define TCGEN05_DEALLOC(t, n) \
    asm volatile("tcgen05.dealloc.cta_group::1.sync.aligned.b32 %0, %1;" :: "r"(t), "r"((uint32_t)(n)))
#define TCGEN05_RELINQ() \
    asm volatile("tcgen05.relinquish_alloc_permit.cta_group::1.sync.aligned;")
#define TCGEN05_COMMIT(mb) \
    asm volatile("tcgen05.commit.cta_group::1.mbarrier::arrive::one.shared::cluster.b64 [%0];" \
                 :: "r"((uint32_t)(mb)) : "memory")
#define TCGEN05_WAIT_LD()  asm volatile("tcgen05.wait::ld.sync.aligned;" ::: "memory")
#define TCGEN05_FENCE_BEFORE() asm volatile("tcgen05.fence::before_thread_sync;" ::: "memory")
#define TCGEN05_FENCE_AFTER()  asm volatile("tcgen05.fence::after_thread_sync;" ::: "memory")
#define FENCE_ASYNC_SHARED() asm volatile("fence.proxy.async.shared::cta;" ::: "memory")
#define MBARRIER_INIT(mb, c) \
    asm volatile("mbarrier.init.shared.b64 [%0], %1;" :: "r"((uint32_t)(mb)), "r"((uint32_t)(c)) : "memory")
#define MBARRIER_INVAL(mb) \
    asm volatile("mbarrier.inval.shared.b64 [%0];" :: "r"((uint32_t)(mb)) : "memory")
#define MBARRIER_WAIT_PARITY(mb, ph) do { \
    uint32_t _mb = (uint32_t)(mb), _ph = (uint32_t)(ph), _done; \
    asm volatile("{\n\t.reg .pred p;\n\tmbarrier.try_wait.parity.acquire.cta.shared::cta.b64 p, [%1], %2;\n\tselp.b32 %0, 1, 0, p;\n\t}" \
        : "=r"(_done) : "r"(_mb), "r"(_ph) : "memory"); \
    if (!_done) { \
        asm volatile("{\n\t.reg .pred P1;\n\tWL_%=: \n\tmbarrier.try_wait.parity.acquire.cta.shared::cta.b64 P1, [%0], %1, 0x989680;\n\t@P1 bra.uni WD_%=;\n\tbra.uni WL_%=;\n\tWD_%=: \n\t}" \
            :: "r"(_mb), "r"(_ph) : "memory"); \
    } \
} while (0)

#define TCGEN05_LD_X32(r, addr) \
    asm volatile("tcgen05.ld.sync.aligned.32x32b.x32.b32 " \
        "{%0, %1, %2, %3, %4, %5, %6, %7, %8, %9, %10, %11, %12, %13, %14, %15, " \
        " %16, %17, %18, %19, %20, %21, %22, %23, %24, %25, %26, %27, %28, %29, %30, %31}, [%32];" \
        : "=r"((r)[0]), "=r"((r)[1]), "=r"((r)[2]), "=r"((r)[3]), "=r"((r)[4]), "=r"((r)[5]), "=r"((r)[6]), "=r"((r)[7]), \
          "=r"((r)[8]), "=r"((r)[9]), "=r"((r)[10]), "=r"((r)[11]), "=r"((r)[12]), "=r"((r)[13]), "=r"((r)[14]), "=r"((r)[15]), \
          "=r"((r)[16]), "=r"((r)[17]), "=r"((r)[18]), "=r"((r)[19]), "=r"((r)[20]), "=r"((r)[21]), "=r"((r)[22]), "=r"((r)[23]), \
          "=r"((r)[24]), "=r"((r)[25]), "=r"((r)[26]), "=r"((r)[27]), "=r"((r)[28]), "=r"((r)[29]), "=r"((r)[30]), "=r"((r)[31]) \
        : "r"(addr))

__device__ __forceinline__ void mma_f16_ss(uint32_t d_tmem, uint64_t a_desc, uint64_t b_desc,
                                           uint32_t idesc, uint32_t enable) {
    asm volatile(
        "{\n\t.reg .pred p;\n\tsetp.ne.u32 p, %5, 0;\n\t"
        "tcgen05.mma.cta_group::1.kind::f16 [%0], %1, %2, %3, {%4, %4, %4, %4}, p;\n\t}"
        :: "r"(d_tmem), "l"(a_desc), "l"(b_desc), "r"(idesc), "r"(0u), "r"(enable)
        : "memory");
}
#endif // HAS_TCGEN05

// ================= CSR build =================
__global__ void zero_cnt_kernel() {
    int i = blockIdx.x * blockDim.x + threadIdx.x;
    if (i < 4 * NNODE) g_cnt[i] = 0;
}
__global__ void hist_kernel(const int* __restrict__ a_src, const int* __restrict__ a_dst,
                            const int* __restrict__ i_src, const int* __restrict__ i_dst, int E) {
    int i = blockIdx.x * blockDim.x + threadIdx.x;
    if (i >= 4 * E) return;
    int w = i / E, e = i - w * E;
    int k = (w == 0) ? a_dst[e] : (w == 1) ? a_src[e] : (w == 2) ? i_dst[e] : i_src[e];
    atomicAdd(&g_cnt[w * NNODE + k], 1);
}
// warp-shuffle scan: 1 block per CSR, 1024 threads, 20 chunks
__global__ void scan_kernel() {
    int c = blockIdx.x;
    __shared__ int wsum[32];
    __shared__ int carry_sh;
    int tid = threadIdx.x, lane = tid & 31, wid = tid >> 5;
    if (tid == 0) { carry_sh = 0; g_off[c * (NNODE + 1)] = 0; }
    __syncthreads();
    for (int base = 0; base < NNODE; base += 1024) {
        int i = base + tid;
        int v = (i < NNODE) ? g_cnt[c * NNODE + i] : 0;
        int x = v;
        #pragma unroll
        for (int d = 1; d < 32; d <<= 1) {
            int t = __shfl_up_sync(0xFFFFFFFF, x, d);
            if (lane >= d) x += t;
        }
        if (lane == 31) wsum[wid] = x;
        __syncthreads();
        if (wid == 0) {
            int s = wsum[lane];
            #pragma unroll
            for (int d = 1; d < 32; d <<= 1) {
                int t = __shfl_up_sync(0xFFFFFFFF, s, d);
                if (lane >= d) s += t;
            }
            wsum[lane] = s;
        }
        __syncthreads();
        int incl = x + (wid > 0 ? wsum[wid - 1] : 0);
        int carry = carry_sh;
        if (i < NNODE) {
            g_off[c * (NNODE + 1) + i + 1] = carry + incl;
            g_cur[c * NNODE + i] = carry + incl - v;
        }
        __syncthreads();
        if (tid == 1023) carry_sh = carry + incl;
        __syncthreads();
    }
}
__global__ void fill_kernel(const int* __restrict__ a_src, const int* __restrict__ a_dst,
                            const int* __restrict__ i_src, const int* __restrict__ i_dst, int E) {
    int i = blockIdx.x * blockDim.x + threadIdx.x;
    if (i >= 4 * E) return;
    int w = i / E, e = i - w * E;
    int k = (w == 0) ? a_dst[e] : (w == 1) ? a_src[e] : (w == 2) ? i_dst[e] : i_src[e];
    int v = (w == 0) ? a_src[e] : (w == 1) ? a_dst[e] : (w == 2) ? i_src[e] : i_dst[e];
    int pos = atomicAdd(&g_cur[w * NNODE + k], 1);
    g_adj[w * E + pos] = v;
}

// ========== fused 4-way segment-mean gather (also zeros BN stats for this layer) ==========
__global__ void gather4_kernel(const __half* __restrict__ Ad, __half* __restrict__ Ap, int E) {
    if (blockIdx.y == 0 && blockIdx.x < 32) {
        int z = blockIdx.x * 64 + threadIdx.x;
        if (z < 4 * FEAT) g_bnstat[z] = 0.f;
    }
    int c = blockIdx.y;
    const __half* src;
    __half* dst;
    int slda, dlda, coff;
    if (c == 0) { src = Ad; slda = 1024; dst = Ap; dlda = 2048; coff = 512; }
    else if (c == 1) { src = Ap; slda = 2048; dst = (__half*)Ad; dlda = 1024; coff = 512; }
    else { src = Ap; slda = 2048; dst = Ap; dlda = 2048; coff = (c == 2) ? 1024 : 1536; }
    int n = blockIdx.x;
    int t = threadIdx.x;            // 0..63, 8 halves each (16B)
    int s = g_off[c * (NNODE + 1) + n];
    int e = g_off[c * (NNODE + 1) + n + 1];
    const int* adj = g_adj + (size_t)c * E;
    float acc[8] = {0.f, 0.f, 0.f, 0.f, 0.f, 0.f, 0.f, 0.f};
    int j = s;
    for (; j + 3 < e; j += 4) {
        int r0 = adj[j], r1 = adj[j + 1], r2 = adj[j + 2], r3 = adj[j + 3];
        uint4 v0 = *(const uint4*)(src + (size_t)r0 * slda + t * 8);
        uint4 v1 = *(const uint4*)(src + (size_t)r1 * slda + t * 8);
        uint4 v2 = *(const uint4*)(src + (size_t)r2 * slda + t * 8);
        uint4 v3 = *(const uint4*)(src + (size_t)r3 * slda + t * 8);
        const uint4* vs[4] = {&v0, &v1, &v2, &v3};
        #pragma unroll
        for (int q = 0; q < 4; q++) {
            const __half2* h2 = (const __half2*)vs[q];
            #pragma unroll
            for (int p = 0; p < 4; p++) {
                float2 f = __half22float2(h2[p]);
                acc[2 * p] += f.x; acc[2 * p + 1] += f.y;
            }
        }
    }
    for (; j < e; j++) {
        int r0 = adj[j];
        uint4 v0 = *(const uint4*)(src + (size_t)r0 * slda + t * 8);
        const __half2* h2 = (const __half2*)&v0;
        #pragma unroll
        for (int p = 0; p < 4; p++) {
            float2 f = __half22float2(h2[p]);
            acc[2 * p] += f.x; acc[2 * p + 1] += f.y;
        }
    }
    float inv = (e > s) ? 1.0f / (float)(e - s) : 0.0f;
    __half o8[8];
    #pragma unroll
    for (int q = 0; q < 8; q++) o8[q] = __float2half_rn(acc[q] * inv);
    *(uint4*)(dst + (size_t)n * dlda + coff + t * 8) = *(uint4*)&o8[0];
}

// ========== mega prep: split2 + wprep + bias in ONE launch ==========
// flat grid: [0,20000) split quads | [20000,21536) wprep tiles | [21536,21538) bias
#define MP_SPLIT 20000
#define MP_WPREP 1536
#define MP_TOTAL (MP_SPLIT + MP_WPREP + 2)
__global__ void mega_prep_kernel(const float* __restrict__ h_p, const float* __restrict__ h_d,
                                 __half* __restrict__ Ap, __half* __restrict__ Ad,
                                 const float* __restrict__ Ws1, const float* __restrict__ Wn1,
                                 const float* __restrict__ Ws2, const float* __restrict__ Wn2,
                                 const float* __restrict__ pWd, const float* __restrict__ pWp,
                                 const float* __restrict__ b1, const float* __restrict__ b2) {
    int b = blockIdx.x;
    int tid = threadIdx.x;
    if (b < MP_SPLIT) {
        int isD = b >= 10000;
        size_t e0 = ((size_t)(isD ? b - 10000 : b) * 256 + tid) * 4;
        const float* src = isD ? h_d : h_p;
        __half* A = isD ? Ad : Ap;
        int lda = isD ? 1024 : 2048;
        float4 v = *(const float4*)(src + e0);
        int row = (int)(e0 >> 9), col = (int)(e0 & 511);
        __half h4[4] = {__float2half_rn(v.x), __float2half_rn(v.y),
                        __float2half_rn(v.z), __float2half_rn(v.w)};
        *(uint2*)(A + (size_t)row * lda + col) = *(uint2*)&h4[0];
    } else if (b < MP_SPLIT + MP_WPREP) {
        int wb = b - MP_SPLIT;
        int which = wb >> 8;             // 0..5
        int rem = wb & 255;
        int n0 = (rem & 15) * 32, k0 = (rem >> 4) * 32;
        int tx = tid & 31, ty = tid >> 5;   // ty 0..7
        __shared__ float tile[4][32][33];
        int nslots;
        __half* B;
        int ldb;
        const float *Ws = nullptr, *Wn = nullptr, *W = nullptr;
        if (which == 0 || which == 2) {
            int li = which >> 1;
            Ws = li ? Ws2 : Ws1; Wn = li ? Wn2 : Wn1;
            nslots = 4; B = g_Bp[li]; ldb = 2048;
        } else if (which == 1 || which == 3) {
            int li = which >> 1;
            Ws = li ? Ws2 : Ws1; Wn = li ? Wn2 : Wn1;
            nslots = 2; B = g_Bd[li]; ldb = 1024;
        } else {
            int q = which - 4;
            W = q ? pWp : pWd;
            nslots = 1; B = g_Bq[q]; ldb = 512;
        }
        #pragma unroll
        for (int r = 0; r < 4; r++) {
            int yy = r * 8 + ty;
            int srcIdx = (k0 + yy) * 512 + (n0 + tx);
            if (which == 0 || which == 2) {
                tile[0][yy][tx] = Ws[srcIdx] + Ws[2 * FF + srcIdx] + Ws[3 * FF + srcIdx];
                tile[1][yy][tx] = Wn[srcIdx];
                tile[2][yy][tx] = Wn[2 * FF + srcIdx];
                tile[3][yy][tx] = Wn[3 * FF + srcIdx];
            } else if (which == 1 || which == 3) {
                tile[0][yy][tx] = Ws[FF + srcIdx];
                tile[1][yy][tx] = Wn[FF + srcIdx];
            } else {
                tile[0][yy][tx] = W[srcIdx];
            }
        }
        __syncthreads();
        #pragma unroll
        for (int r = 0; r < 4; r++) {
            int yy = r * 8 + ty;
            for (int sl = 0; sl < nslots; sl++) {
                float v = tile[sl][tx][yy];
                size_t o = (size_t)(n0 + yy) * ldb + sl * 512 + k0 + tx;
                B[o] = __float2half_rn(v);
            }
        }
    } else {
        int half = b - MP_SPLIT - MP_WPREP;   // 0 or 1
        int i = half * 256 + tid;
        g_biasP[0][i] = b1[i] + b1[1024 + i] + b1[1536 + i];
        g_biasD[0][i] = b1[512 + i];
        g_biasP[1][i] = b2[i] + b2[1024 + i] + b2[1536 + i];
        g_biasD[1][i] = b2[512 + i];
    }
}

// ================= paired tcgen05 fp16 GEMM, M=128 x N=256, KC=32, 4-stage, 2 CTA/SM ====
// C = A16 * B16 + bias (fp32 TMEM accum, 256 TMEM cols per CTA)
struct GPair {
    const __half *A0, *B0; const float* bias0; float* C0; int lda0, ldb0, K0;
    const __half *A1, *B1; const float* bias1; float* C1; int lda1, ldb1, K1;
};
#define STAGE_BYTES 24576   // A 8K | B 16K
#define GEMM_SMEM (1024 + 4 * STAGE_BYTES)   // 99,328 B -> 2 CTAs/SM
__global__ __launch_bounds__(128)
void mma_gemm_pair(const GPair gp, int M) {
    const __half* A   = blockIdx.z ? gp.A1 : gp.A0;
    const __half* B   = blockIdx.z ? gp.B1 : gp.B0;
    const float* bias = blockIdx.z ? gp.bias1 : gp.bias0;
    float* C = blockIdx.z ? gp.C1 : gp.C0;
    const int lda = blockIdx.z ? gp.lda1 : gp.lda0;
    const int ldb = blockIdx.z ? gp.ldb1 : gp.ldb0;
    const int Ktot = blockIdx.z ? gp.K1 : gp.K0;
#if HAS_TCGEN05
    extern __shared__ char smem[];
    uint32_t sb = smem_to_u32(smem);
    const int tid = threadIdx.x;
    const int wid = tid >> 5, lid = tid & 31;
    const int m0 = blockIdx.y * 128, n0 = blockIdx.x * 256;

    if (wid == 0) { TCGEN05_ALLOC(sb, 256); TCGEN05_RELINQ(); }
    if (tid == 0) MBARRIER_INIT(sb + 8, 1);
    __syncthreads();
    uint32_t tbase;
    asm volatile("ld.shared.b32 %0, [%1];" : "=r"(tbase) : "r"(sb));

    const uint32_t idesc = 0x8400010u;   // F32 acc, F16 A/B, M=128, N=256
    const int nst = Ktot >> 5;           // KC = 32

    auto issue_loads = [&](int s) {
        int k0 = s << 5;
        uint32_t base = sb + 1024 + (uint32_t)(s & 3) * STAGE_BYTES;
        #pragma unroll
        for (int c = 0; c < 4; c++) {
            int chunk = c * 128 + tid;
            int row = chunk >> 2, ch = chunk & 3;
            uint32_t sw = SMEM_SWIZZLE_64B((uint32_t)(row * 64 + ch * 16));
            size_t ga = (size_t)(m0 + row) * lda + k0 + ch * 8;
            CP_ASYNC16(base + sw, A + ga);
        }
        #pragma unroll
        for (int c = 0; c < 8; c++) {
            int chunk = c * 128 + tid;
            int row = chunk >> 2, ch = chunk & 3;
            uint32_t sw = SMEM_SWIZZLE_64B((uint32_t)(row * 64 + ch * 16));
            size_t gb = (size_t)(n0 + row) * ldb + k0 + ch * 8;
            CP_ASYNC16(base + 8192 + sw, B + gb);
        }
        CP_COMMIT();
    };

    issue_loads(0);
    issue_loads(1);
    issue_loads(2);
    for (int s = 0; s < nst; s++) {
        if (s >= 1) MBARRIER_WAIT_PARITY(sb + 8, (s - 1) & 1);
        if (s + 3 < nst)      { issue_loads(s + 3); CP_WAIT3(); }
        else if (s + 2 < nst) { CP_WAIT2(); }
        else if (s + 1 < nst) { CP_WAIT1(); }
        else                  { CP_WAIT0(); }
        __syncthreads();
        FENCE_ASYNC_SHARED();
        if (wid == 0 && elect_one_pred()) {
            uint32_t bufb = sb + 1024 + (uint32_t)(s & 3) * STAGE_BYTES;
            uint64_t dA = MAKE_SMEM_DESC64(bufb);
            uint64_t dB = MAKE_SMEM_DESC64(bufb + 8192);
            #pragma unroll
            for (int kk = 0; kk < 2; kk++) {
                uint64_t o = (uint64_t)(kk * 2);
                mma_f16_ss(tbase, dA + o, dB + o, idesc, !(s == 0 && kk == 0));
            }
            TCGEN05_COMMIT(sb + 8);
        }
    }
    MBARRIER_WAIT_PARITY(sb + 8, (nst - 1) & 1);
    TCGEN05_FENCE_AFTER();

    int gr = m0 + wid * 32 + lid;
    #pragma unroll
    for (int base = 0; base < 256; base += 32) {
        uint32_t r[32];
        TCGEN05_LD_X32(r, tbase + base);
        TCGEN05_WAIT_LD();
        if (gr < M) {
            float* cp = C + (size_t)gr * 512 + n0 + base;
            #pragma unroll
            for (int j = 0; j < 32; j += 4) {
                float4 v;
                v.x = __uint_as_float(r[j + 0]) + bias[n0 + base + j + 0];
                v.y = __uint_as_float(r[j + 1]) + bias[n0 + base + j + 1];
                v.z = __uint_as_float(r[j + 2]) + bias[n0 + base + j + 2];
                v.w = __uint_as_float(r[j + 3]) + bias[n0 + base + j + 3];
                *(float4*)(cp + j) = v;
            }
        }
    }
    TCGEN05_FENCE_BEFORE();
    __syncthreads();
    if (tid == 0) MBARRIER_INVAL(sb + 8);
    __syncthreads();
    if (wid == 0) TCGEN05_DEALLOC(tbase, 256);
#else
    const int tid = threadIdx.x;
    const int m0 = blockIdx.y * 128, n0 = blockIdx.x * 256;
    for (int rc = tid; rc < 128 * 256; rc += blockDim.x) {
        int r = rc >> 8, c = rc & 255;
        int gr = m0 + r, gc = n0 + c;
        if (gr >= M) continue;
        const __half* a = A + (size_t)gr * lda;
        const __half* b = B + (size_t)gc * ldb;
        float acc = 0.f;
        for (int k = 0; k < Ktot; k++)
            acc += __half2float(a[k]) * __half2float(b[k]);
        C[(size_t)gr * 512 + gc] = acc + bias[gc];
    }
#endif
}

// ================= BatchNorm + ReLU (merged d+p) =================
__global__ void bn_reduce2_kernel(const float* __restrict__ xd, const float* __restrict__ xp) {
    int gcol = blockIdx.x * 256 + threadIdx.x;   // 0..1023
    int isP = gcol >= 512;
    int col = gcol & 511;
    const float* x = isP ? xp : xd;
    float s = 0.f, s2 = 0.f;
    for (int r = blockIdx.y; r < NNODE; r += gridDim.y) {
        float v = x[(size_t)r * FEAT + col];
        s += v; s2 += v * v;
    }
    int base = isP ? 1024 : 0;
    atomicAdd(&g_bnstat[base + col], s);
    atomicAdd(&g_bnstat[base + 512 + col], s2);
}
__global__ void bn_norm2_kernel(const float* __restrict__ rawd, const float* __restrict__ rawp,
                                __half* __restrict__ Ad, __half* __restrict__ Ap,
                                const float* __restrict__ gamma_l, const float* __restrict__ beta_l) {
    size_t idx = (size_t)blockIdx.x * blockDim.x + threadIdx.x;
    if (idx >= (size_t)NNODE * FEAT) return;
    int isP = blockIdx.y;
    int col = (int)(idx & (FEAT - 1));
    int row = (int)(idx >> 9);
    const float* raw = isP ? rawp : rawd;
    __half* Ax = isP ? Ap : Ad;
    int lda = isP ? 2048 : 1024;
    int sbase = isP ? 1024 : 0;
    const float* gamma = gamma_l + isP * FEAT;
    const float* beta  = beta_l + isP * FEAT;
    float mean = g_bnstat[sbase + col] * (1.0f / NNODE);
    float var  = g_bnstat[sbase + 512 + col] * (1.0f / NNODE) - mean * mean;
    float sc = gamma[col] * rsqrtf(var + BN_EPS);
    float v = (raw[idx] - mean) * sc + beta[col];
    v = v > 0.f ? v : 0.f;
    Ax[(size_t)row * lda + col] = __float2half_rn(v);
}

// ================= host orchestration =================
extern "C" void kernel_launch(void* const* d_in, const int* in_sizes, int n_in,
                              void* d_out, int out_size) {
    const float* h_d  = (const float*)d_in[0];
    const float* h_p  = (const float*)d_in[1];
    const float* Ws1  = (const float*)d_in[2];
    const float* Wn1  = (const float*)d_in[3];
    const float* b1   = (const float*)d_in[4];
    const float* Ws2  = (const float*)d_in[5];
    const float* Wn2  = (const float*)d_in[6];
    const float* b2   = (const float*)d_in[7];
    const float* gam  = (const float*)d_in[8];
    const float* bet  = (const float*)d_in[9];
    const float* pWd  = (const float*)d_in[10];
    const float* pbd  = (const float*)d_in[11];
    const float* pWp  = (const float*)d_in[12];
    const float* pbp  = (const float*)d_in[13];
    const int* a_src = (const int*)d_in[14];
    const int* a_dst = (const int*)d_in[15];
    const int* i_src = (const int*)d_in[16];
    const int* i_dst = (const int*)d_in[17];
    int E = in_sizes[14];

    float* out_d = (float*)d_out;
    float* out_p = out_d + (size_t)NNODE * FEAT;

    __half *Ap, *Ad, *Bp, *Bd, *Bq;
    float *rawd, *rawp, *biasP, *biasD;
    cudaGetSymbolAddress((void**)&Ap, g_Ap);
    cudaGetSymbolAddress((void**)&Ad, g_Ad);
    cudaGetSymbolAddress((void**)&Bp, g_Bp);
    cudaGetSymbolAddress((void**)&Bd, g_Bd);
    cudaGetSymbolAddress((void**)&Bq, g_Bq);
    cudaGetSymbolAddress((void**)&rawd, g_rawd);
    cudaGetSymbolAddress((void**)&rawp, g_rawp);
    cudaGetSymbolAddress((void**)&biasP, g_biasP);
    cudaGetSymbolAddress((void**)&biasD, g_biasD);

    cudaFuncSetAttribute(mma_gemm_pair, cudaFuncAttributeMaxDynamicSharedMemorySize, GEMM_SMEM);

    const int NW = (NNODE * FEAT + 255) / 256;
    const int MT = (NNODE + 127) / 128;               // 157
    const dim3 gpair(2, MT, 2);
    const dim3 g4(NNODE, 4);

    GPair lay[2];
    for (int li = 0; li < 2; li++) {
        lay[li].A0 = Ap; lay[li].B0 = Bp + (size_t)li * 512 * 2048;
        lay[li].bias0 = biasP + li * FEAT; lay[li].C0 = rawp;
        lay[li].lda0 = 2048; lay[li].ldb0 = 2048; lay[li].K0 = 2048;
        lay[li].A1 = Ad; lay[li].B1 = Bd + (size_t)li * 512 * 1024;
        lay[li].bias1 = biasD + li * FEAT; lay[li].C1 = rawd;
        lay[li].lda1 = 1024; lay[li].ldb1 = 1024; lay[li].K1 = 1024;
    }
    GPair proj;
    proj.A0 = Ad; proj.B0 = Bq;
    proj.bias0 = pbd; proj.C0 = out_d; proj.lda0 = 1024; proj.ldb0 = 512; proj.K0 = 512;
    proj.A1 = Ap; proj.B1 = Bq + FF;
    proj.bias1 = pbp; proj.C1 = out_p; proj.lda1 = 2048; proj.ldb1 = 512; proj.K1 = 512;

    // ---- fork: CSR chain on cudaStreamPerThread (predefined handle, no creation) ----
    cudaEvent_t evRoot, evC;
    cudaEventCreateWithFlags(&evRoot, cudaEventDisableTiming);
    cudaEventCreateWithFlags(&evC, cudaEventDisableTiming);

    cudaEventRecord(evRoot, 0);
    cudaStreamWaitEvent(cudaStreamPerThread, evRoot, 0);

    zero_cnt_kernel<<<(4 * NNODE + 255) / 256, 256, 0, cudaStreamPerThread>>>();
    hist_kernel<<<(4 * E + 255) / 256, 256, 0, cudaStreamPerThread>>>(a_src, a_dst, i_src, i_dst, E);
    scan_kernel<<<4, 1024, 0, cudaStreamPerThread>>>();
    fill_kernel<<<(4 * E + 255) / 256, 256, 0, cudaStreamPerThread>>>(a_src, a_dst, i_src, i_dst, E);
    cudaEventRecord(evC, cudaStreamPerThread);

    // main stream: fused prep (split + wprep + bias)
    mega_prep_kernel<<<MP_TOTAL, 256>>>(h_p, h_d, Ap, Ad,
                                        Ws1, Wn1, Ws2, Wn2, pWd, pWp, b1, b2);

    cudaStreamWaitEvent(0, evC, 0);   // join: CSR ready before gather

    // ---- layers ----
    for (int li = 0; li < 2; li++) {
        gather4_kernel<<<g4, 64>>>(Ad, Ap, E);   // also zeros g_bnstat
        mma_gemm_pair<<<gpair, 128, GEMM_SMEM>>>(lay[li], NNODE);
        bn_reduce2_kernel<<<dim3(4, 64), 256>>>(rawd, rawp);
        bn_norm2_kernel<<<dim3(NW, 2), 256>>>(rawd, rawp, Ad, Ap,
                                              gam + li * 2 * FEAT, bet + li * 2 * FEAT);
    }

    // ---- projections ----
    mma_gemm_pair<<<gpair, 128, GEMM_SMEM>>>(proj, NNODE);

    // destroy events (host-side objects; safe during capture — graph holds its own refs)
    cudaEventDestroy(evRoot);
    cudaEventDestroy(evC);
}